// round 6
// baseline (speedup 1.0000x reference)
#include <cuda_runtime.h>
#include <cuda_bf16.h>
#include <math.h>

#define B_ 16
#define T_ 2048
#define N_ 64

// Output layout (flattened tuple in order)
#define SEED_OFF 0
#define GCN_OFF  2097152
#define FREQ_OFF 4194304
#define IMP_OFF  6291456
#define COMP_OFF 8388608
#define GATE_OFF 10485760
#define ADJ_OFF  14680064

typedef unsigned long long u64;
typedef unsigned int u32;

// Scratch (static device arrays: allowed)
__device__ float  g_adj[N_ * N_];
__device__ float2 g_preb1p[32 * N_];
__device__ float  g_first[65536], g_last[65536];
__device__ unsigned char g_has[65536];
__device__ float  g_pref[65536], g_suf[65536];
__device__ unsigned char g_prefh[65536], g_sufh[65536];

// ---- packed f32x2 helpers ---------------------------------------------------
__device__ __forceinline__ u64 pk2(float lo, float hi) {
    u64 r; asm("mov.b64 %0, {%1, %2};" : "=l"(r) : "f"(lo), "f"(hi)); return r;
}
__device__ __forceinline__ void upk2(u64 v, float& lo, float& hi) {
    asm("mov.b64 {%0, %1}, %2;" : "=f"(lo), "=f"(hi) : "l"(v));
}
__device__ __forceinline__ u64 ffma2(u64 a, u64 b, u64 c) {
    u64 d; asm("fma.rn.f32x2 %0, %1, %2, %3;" : "=l"(d) : "l"(a), "l"(b), "l"(c)); return d;
}
__device__ __forceinline__ u64 mul2(u64 a, u64 b) {
    u64 d; asm("mul.rn.f32x2 %0, %1, %2;" : "=l"(d) : "l"(a), "l"(b)); return d;
}

__device__ __forceinline__ float tanh_ap(float x) {
    float t; asm("tanh.approx.f32 %0, %1;" : "=f"(t) : "f"(x)); return t;
}

// scalar tanh-approx gelu
__device__ __forceinline__ float gelu_t(float x) {
    float x2 = x * x;
    float inner = fmaf(x2, 0.035677408136f, 0.7978845608028654f);
    float b = x * inner;
    float t = tanh_ap(b);
    float hx = 0.5f * x;
    return fmaf(hx, t, hx);
}

// packed pairwise gelu: 5 packed fma-pipe ops + 2 MUFU
__device__ __forceinline__ u64 gelu2(u64 x) {
    const u64 C1 = pk2(0.035677408136f, 0.035677408136f);
    const u64 C0 = pk2(0.7978845608028654f, 0.7978845608028654f);
    const u64 H  = pk2(0.5f, 0.5f);
    u64 x2 = mul2(x, x);
    u64 inner = ffma2(x2, C1, C0);
    u64 b = mul2(x, inner);
    float b0, b1; upk2(b, b0, b1);
    u64 t = pk2(tanh_ap(b0), tanh_ap(b1));
    u64 hx = mul2(x, H);
    return ffma2(hx, t, hx);
}

__device__ __forceinline__ u32 to_tf32(float v) {
    u32 r; asm("cvt.rna.tf32.f32 %0, %1;" : "=r"(r) : "f"(v)); return r;
}

__device__ __forceinline__ void mma_tf32(float* d,
    u32 a0, u32 a1, u32 a2, u32 a3, u32 b0, u32 b1)
{
    asm("mma.sync.aligned.m16n8k8.row.col.f32.tf32.tf32.f32 "
        "{%0,%1,%2,%3}, {%4,%5,%6,%7}, {%8,%9}, {%0,%1,%2,%3};"
        : "+f"(d[0]), "+f"(d[1]), "+f"(d[2]), "+f"(d[3])
        : "r"(a0), "r"(a1), "r"(a2), "r"(a3), "r"(b0), "r"(b1));
}

// ---------------------------------------------------------------------------
// Fill stage 1
// ---------------------------------------------------------------------------
__global__ void __launch_bounds__(256) fill_sum_kernel(
    const float* __restrict__ x, const float* __restrict__ mask)
{
    int g = blockIdx.x * 256 + threadIdx.x;
    int n = g & 63;
    int c = (g >> 6) & 63;
    int b = g >> 12;
    int base = ((b * T_) + c * 32) * N_ + n;
    float first = 0.f, last = 0.f; bool has = false;
    #pragma unroll
    for (int t = 0; t < 32; ++t) {
        int idx = base + t * N_;
        float v = x[idx];
        bool obs = (mask[idx] == 0.f);
        if (obs) { if (!has) first = v; last = v; has = true; }
    }
    g_first[g] = first; g_last[g] = last; g_has[g] = (unsigned char)has;
}

// ---------------------------------------------------------------------------
// Fill stage 2
// ---------------------------------------------------------------------------
__global__ void __launch_bounds__(256) fill_scan_kernel()
{
    int g = blockIdx.x * 256 + threadIdx.x;
    int b = g >> 6, n = g & 63;
    int base = b * 4096 + n;
    float pv = 0.f; bool ph = false;
    #pragma unroll 8
    for (int c = 0; c < 64; ++c) {
        int i = base + c * 64;
        g_pref[i] = pv; g_prefh[i] = (unsigned char)ph;
        if (g_has[i]) { pv = g_last[i]; ph = true; }
    }
    float sv = 0.f; bool sh = false;
    #pragma unroll 8
    for (int c = 63; c >= 0; --c) {
        int i = base + c * 64;
        g_suf[i] = sv; g_sufh[i] = (unsigned char)sh;
        if (g_has[i]) { sv = g_first[i]; sh = true; }
    }
}

// ---------------------------------------------------------------------------
// Fill stage 3
// ---------------------------------------------------------------------------
__global__ void __launch_bounds__(256) fill_out_kernel(
    const float* __restrict__ x, const float* __restrict__ mask,
    float* __restrict__ seed)
{
    int g = blockIdx.x * 256 + threadIdx.x;
    int n = g & 63;
    int c = (g >> 6) & 63;
    int b = g >> 12;
    int base = ((b * T_) + c * 32) * N_ + n;

    float fv = g_pref[g]; bool fh = (bool)g_prefh[g];
    float vals[32];
    unsigned obsm = 0u, fam = 0u;
    #pragma unroll
    for (int t = 0; t < 32; ++t) {
        int idx = base + t * N_;
        float v = x[idx];
        bool obs = (mask[idx] == 0.f);
        if (obs) { fv = v; fh = true; obsm |= (1u << t); }
        vals[t] = fv;
        if (fh) fam |= (1u << t);
    }
    float bv = g_suf[g]; bool bh = (bool)g_sufh[g];
    #pragma unroll
    for (int t = 31; t >= 0; --t) {
        bool obs = (obsm >> t) & 1u;
        bool fa  = (fam  >> t) & 1u;
        float v = vals[t];
        if (obs) { bv = v; bh = true; }
        float out;
        if (obs)            out = v;
        else if (fa && bh)  out = 0.5f * (v + bv);
        else if (fa)        out = v;
        else if (bh)        out = bv;
        else                out = 0.f;
        seed[base + t * N_] = out;
    }
}

// ---------------------------------------------------------------------------
// Kernel 2: adjacency + rate-embed pre-bias
// ---------------------------------------------------------------------------
__global__ void __launch_bounds__(64) adj_kernel(
    const float* __restrict__ emb, const int* __restrict__ rate_id,
    const float* __restrict__ rate_table, const float* __restrict__ gw1,
    const float* __restrict__ gb1, float* __restrict__ out_adj)
{
    __shared__ float sE[64 * 32];
    int tid = threadIdx.x;
    for (int i = tid; i < 64 * 32; i += 64) sE[i] = emb[i];
    __syncthreads();

    float sc[64];
    float mx = -1e30f;
    #pragma unroll
    for (int m = 0; m < 64; ++m) {
        float d = 0.f;
        #pragma unroll
        for (int h = 0; h < 32; ++h) d = fmaf(sE[tid * 32 + h], sE[m * 32 + h], d);
        d = fmaxf(d, 0.f);
        sc[m] = d; mx = fmaxf(mx, d);
    }
    float sum = 0.f;
    #pragma unroll
    for (int m = 0; m < 64; ++m) { float e = __expf(sc[m] - mx); sc[m] = e; sum += e; }
    float inv = 1.0f / sum;
    #pragma unroll
    for (int m = 0; m < 64; ++m) {
        float a = sc[m] * inv;
        g_adj[tid * 64 + m] = a;
        out_adj[tid * 64 + m] = a;
    }
    int rid = rate_id[tid];
    for (int j2 = 0; j2 < 32; ++j2) {
        float v0 = gb1[2 * j2], v1 = gb1[2 * j2 + 1];
        #pragma unroll
        for (int e = 0; e < 16; ++e) {
            float rt = rate_table[rid * 16 + e];
            v0 = fmaf(rt, gw1[(6 + e) * 64 + 2 * j2], v0);
            v1 = fmaf(rt, gw1[(6 + e) * 64 + 2 * j2 + 1], v1);
        }
        g_preb1p[j2 * 64 + tid] = make_float2(v0, v1);
    }
}

// ---------------------------------------------------------------------------
// Kernel 3: packed-pair radix-2 FFT filter
// ---------------------------------------------------------------------------
__global__ void __launch_bounds__(256) fft_kernel(
    const float* __restrict__ seed, const float* __restrict__ fre,
    const float* __restrict__ fim, float* __restrict__ xfreq)
{
    __shared__ float re[2048], im[2048], twr[1024], twi[1024];
    int tid = threadIdx.x;
    int b = blockIdx.x >> 5;
    int p = blockIdx.x & 31;
    int n0 = p * 2;
    const float* src = seed + (size_t)b * T_ * N_ + n0;

    for (int j = tid; j < 1024; j += 256) {
        float s, c;
        sincosf(-6.28318530717958647692f * (float)j * (1.0f / 2048.0f), &s, &c);
        twr[j] = c; twi[j] = s;
    }
    for (int t = tid; t < 2048; t += 256) {
        float2 v = *(const float2*)(src + (size_t)t * N_);
        re[t] = v.x; im[t] = v.y;
    }

    for (int s = 10; s >= 0; --s) {
        int half = 1 << s;
        __syncthreads();
        for (int bi = tid; bi < 1024; bi += 256) {
            int j = bi & (half - 1);
            int i1 = ((bi >> s) << (s + 1)) | j;
            int i2 = i1 + half;
            int tj = j << (10 - s);
            float wr = twr[tj], wi = twi[tj];
            float ar = re[i1], ai = im[i1], br = re[i2], b2 = im[i2];
            re[i1] = ar + br; im[i1] = ai + b2;
            float dr = ar - br, di = ai - b2;
            re[i2] = dr * wr - di * wi;
            im[i2] = dr * wi + di * wr;
        }
    }
    __syncthreads();

    for (int k = tid; k <= 1024; k += 256) {
        int km = (2048 - k) & 2047;
        int pk = __brev(k) >> 21;
        int pm = __brev(km) >> 21;
        float zr = re[pk], zi = im[pk];
        float yr = re[pm], yi = im[pm];
        float x1r = 0.5f * (zr + yr), x1i = 0.5f * (zi - yi);
        float x2r = 0.5f * (zi + yi), x2i = 0.5f * (yr - zr);
        float h1r = fre[(size_t)k * N_ + n0],     h1i = fim[(size_t)k * N_ + n0];
        float h2r = fre[(size_t)k * N_ + n0 + 1], h2i = fim[(size_t)k * N_ + n0 + 1];
        float y1r = x1r * h1r - x1i * h1i, y1i = x1r * h1i + x1i * h1r;
        float y2r = x2r * h2r - x2i * h2i, y2i = x2r * h2i + x2i * h2r;
        if (k == 0 || k == 1024) { y1i = 0.f; y2i = 0.f; }
        re[pk] = y1r - y2i; im[pk] = y1i + y2r;
        if (k > 0 && k < 1024) { re[pm] = y1r + y2i; im[pm] = y2r - y1i; }
    }

    for (int s = 0; s <= 10; ++s) {
        int half = 1 << s;
        __syncthreads();
        for (int bi = tid; bi < 1024; bi += 256) {
            int j = bi & (half - 1);
            int i1 = ((bi >> s) << (s + 1)) | j;
            int i2 = i1 + half;
            int tj = j << (10 - s);
            float wr = twr[tj], wi = -twi[tj];
            float br = re[i2], b2 = im[i2];
            float tr = br * wr - b2 * wi, ti = br * wi + b2 * wr;
            float ar = re[i1], ai = im[i1];
            re[i1] = ar + tr; im[i1] = ai + ti;
            re[i2] = ar - tr; im[i2] = ai - ti;
        }
    }
    __syncthreads();

    float* dst = xfreq + (size_t)b * T_ * N_ + n0;
    const float scl = 1.0f / 2048.0f;
    for (int t = tid; t < 2048; t += 256) {
        float2 v; v.x = re[t] * scl; v.y = im[t] * scl;
        *(float2*)(dst + (size_t)t * N_) = v;
    }
}

// ---------------------------------------------------------------------------
// Kernel 4 v6: persistent; tf32 mma layer2; u64 weight loads; permuted w2
// for vectorized B-fragment LDS; next-tile input prefetch under phase B.
// ---------------------------------------------------------------------------
#define FTH 512
#define HS_S 520
#define W2_S 72
#define NTILES (B_ * T_ * N_ / FTH)   // 4096
#define PGRID 148
#define SMEM_BYTES (49444 * 4)

__global__ void __launch_bounds__(FTH, 1) fused_kernel(
    const float* __restrict__ seed, const float* __restrict__ mask,
    const float* __restrict__ xin, const float* __restrict__ xfreq,
    const float* __restrict__ gw1, const float* __restrict__ gw2,
    const float* __restrict__ gb2, const float* __restrict__ gw3,
    const float* __restrict__ gb3,
    const float* __restrict__ gcw1, const float* __restrict__ gcb1,
    const float* __restrict__ gcw2, const float* __restrict__ gcb2,
    float* __restrict__ out_gcn, float* __restrict__ out_imp,
    float* __restrict__ out_comp, float* __restrict__ out_gate)
{
    extern __shared__ float sm[];
    float* hs    = sm;                    // [64][520] (tf32 bits)
    float* sW2   = hs    + 64 * HS_S;     // [64][72] (tf32 bits, j-permuted)
    float* sA    = sW2   + 64 * W2_S;     // [64][66]
    float* sPreb = sA    + 64 * 66;       // [32][64] float2
    float* sW1   = sPreb + 4096;          // [6][64]
    float* sW3e  = sW1   + 384;           // [32] float2
    float* sW3o  = sW3e  + 64;            // [32] float2
    float* sB2   = sW3o  + 64;            // [64]
    float* sGc   = sB2   + 64;            // [96]
    float* sPm   = sGc   + 96;            // [8][64]
    float* sXg   = sPm   + FTH;
    float* sXf   = sXg   + FTH;
    float* sMm   = sXf   + FTH;
    float* sXi   = sMm   + FTH;
    float* sCst  = sXi   + FTH;           // [4]

    int tid = threadIdx.x;

    // ---- stage weights once ----
    for (int i = tid; i < 4096; i += FTH) {
        int k = i >> 6, j = i & 63;
        int jp = (j & 7) * 8 + (j >> 3);          // permuted column
        ((u32*)sW2)[k * W2_S + jp] = to_tf32(gw2[i]);
    }
    for (int i = tid; i < 4096; i += FTH) sA[(i >> 6) * 66 + (i & 63)] = g_adj[i];
    for (int i = tid; i < 2048; i += FTH) ((float2*)sPreb)[i] = g_preb1p[i];
    if (tid < 384) sW1[tid] = gw1[tid];
    if (tid < 32) {
        ((float2*)sW3e)[tid] = make_float2(gw3[4 * tid],     gw3[4 * tid + 2]);
        ((float2*)sW3o)[tid] = make_float2(gw3[4 * tid + 1], gw3[4 * tid + 3]);
        sGc[tid] = gcw1[tid]; sGc[32 + tid] = gcb1[tid]; sGc[64 + tid] = gcw2[tid];
    }
    if (tid < 64) sB2[tid] = gb2[tid];
    if (tid == 0) { sCst[0] = gcb2[0]; sCst[1] = gb3[0]; sCst[2] = gb3[1]; }

    int n    = tid & 63;
    int r    = tid >> 6;      // 0..7
    int lane = tid & 31;
    int warp = tid >> 5;      // 0..15
    int m0   = warp * 32;
    int qr   = lane >> 2;     // quad row 0..7
    int qc   = lane & 3;      // quad col 0..3

    // preload first tile inputs
    int tile0 = blockIdx.x;
    float s = 0.f, mm = 0.f, xf = 0.f, xi = 0.f;
    {
        int gidx = tile0 * FTH + tid;
        s  = seed[gidx];
        mm = mask[gidx];
        xf = xfreq[gidx];
        xi = xin[gidx];
    }

    for (int tile = tile0; tile < NTILES; tile += PGRID) {
        __syncthreads();

        int gidx = tile * FTH + tid;

        // ---- phi(s), packed pairs ----
        u64 sp = pk2(s, s);
        u64 accp = pk2(0.f, 0.f);
        const u64* gcW = (const u64*)sGc;
        const u64* gcB = (const u64*)(sGc + 32);
        const u64* gcV = (const u64*)(sGc + 64);
        #pragma unroll
        for (int hq = 0; hq < 16; ++hq) {
            u64 pre = ffma2(sp, gcW[hq], gcB[hq]);
            accp = ffma2(gelu2(pre), gcV[hq], accp);
        }
        float p0, p1; upk2(accp, p0, p1);
        sPm[r * 64 + n] = p0 + p1;
        __syncthreads();

        // ---- x_gcn (packed matvec) ----
        u64 xgp = pk2(0.f, 0.f);
        const u64* arow = (const u64*)(sA + n * 66);
        const u64* prow = (const u64*)(sPm + r * 64);
        #pragma unroll 8
        for (int m2 = 0; m2 < 32; ++m2)
            xgp = ffma2(arow[m2], prow[m2], xgp);
        float xg0, xg1; upk2(xgp, xg0, xg1);
        float xg = xg0 + xg1 + sCst[0];

        sXg[tid] = xg; sXf[tid] = xf; sMm[tid] = mm; sXi[tid] = xi;
        out_gcn[gidx] = xg;

        // ---- layer1 (packed, u64 weight loads) -> hs as tf32 ----
        u64 u0 = pk2(s, s), u1 = pk2(mm, mm), u2 = pk2(xg, xg);
        u64 u3 = pk2(xf, xf), u4 = pk2(xg - s, xg - s), u5 = pk2(xf - s, xf - s);
        const u64* W1p = (const u64*)sW1;             // [6][32] pairs
        const u64* prebp = (const u64*)sPreb;
        u32* hsu = (u32*)hs;
        #pragma unroll
        for (int jq = 0; jq < 16; ++jq) {
            u64 a0 = prebp[(2 * jq) * 64 + n];
            u64 a1 = prebp[(2 * jq + 1) * 64 + n];
            int p2 = jq * 2;
            a0 = ffma2(u0, W1p[0 * 32 + p2], a0); a1 = ffma2(u0, W1p[0 * 32 + p2 + 1], a1);
            a0 = ffma2(u1, W1p[1 * 32 + p2], a0); a1 = ffma2(u1, W1p[1 * 32 + p2 + 1], a1);
            a0 = ffma2(u2, W1p[2 * 32 + p2], a0); a1 = ffma2(u2, W1p[2 * 32 + p2 + 1], a1);
            a0 = ffma2(u3, W1p[3 * 32 + p2], a0); a1 = ffma2(u3, W1p[3 * 32 + p2 + 1], a1);
            a0 = ffma2(u4, W1p[4 * 32 + p2], a0); a1 = ffma2(u4, W1p[4 * 32 + p2 + 1], a1);
            a0 = ffma2(u5, W1p[5 * 32 + p2], a0); a1 = ffma2(u5, W1p[5 * 32 + p2 + 1], a1);
            u64 g0 = gelu2(a0);
            u64 g1 = gelu2(a1);
            float v0, v1, v2, v3;
            upk2(g0, v0, v1); upk2(g1, v2, v3);
            hsu[(4 * jq + 0) * HS_S + tid] = to_tf32(v0);
            hsu[(4 * jq + 1) * HS_S + tid] = to_tf32(v1);
            hsu[(4 * jq + 2) * HS_S + tid] = to_tf32(v2);
            hsu[(4 * jq + 3) * HS_S + tid] = to_tf32(v3);
        }
        __syncthreads();

        // ---- prefetch next tile inputs (hidden under phase B) ----
        int ntile = tile + PGRID;
        float s_n = 0.f, mm_n = 0.f, xf_n = 0.f, xi_n = 0.f;
        if (ntile < NTILES) {
            int gidx2 = ntile * FTH + tid;
            s_n  = seed[gidx2];
            mm_n = mask[gidx2];
            xf_n = xfreq[gidx2];
            xi_n = xin[gidx2];
        }

        // ---- Phase B: layer2 via tf32 mma ----
        float acc[2][8][4];
        #pragma unroll
        for (int n8 = 0; n8 < 8; ++n8) {
            int j0 = n8 * 8 + qc * 2;
            float2 bb = *(const float2*)(sB2 + j0);
            #pragma unroll
            for (int mt = 0; mt < 2; ++mt) {
                acc[mt][n8][0] = bb.x; acc[mt][n8][1] = bb.y;
                acc[mt][n8][2] = bb.x; acc[mt][n8][3] = bb.y;
            }
        }

        const u32* hsub = (const u32*)hs;
        const u32* w2u  = (const u32*)sW2;
        int ar = m0 + qr;
        #pragma unroll
        for (int k8 = 0; k8 < 8; ++k8) {
            int kb = k8 * 8 + qc;
            const u32* h0 = hsub + kb * HS_S;
            const u32* h4 = hsub + (kb + 4) * HS_S;
            u32 a00 = h0[ar],      a01 = h0[ar + 8],  a02 = h4[ar],      a03 = h4[ar + 8];
            u32 a10 = h0[ar + 16], a11 = h0[ar + 24], a12 = h4[ar + 16], a13 = h4[ar + 24];
            // vectorized B-fragment loads (w2 j-permuted: thread's 8 cols contiguous)
            uint4 bA0 = *(const uint4*)(w2u + kb * W2_S + qr * 8);
            uint4 bA1 = *(const uint4*)(w2u + kb * W2_S + qr * 8 + 4);
            uint4 bB0 = *(const uint4*)(w2u + (kb + 4) * W2_S + qr * 8);
            uint4 bB1 = *(const uint4*)(w2u + (kb + 4) * W2_S + qr * 8 + 4);
            u32 b0a[8] = {bA0.x, bA0.y, bA0.z, bA0.w, bA1.x, bA1.y, bA1.z, bA1.w};
            u32 b1a[8] = {bB0.x, bB0.y, bB0.z, bB0.w, bB1.x, bB1.y, bB1.z, bB1.w};
            #pragma unroll
            for (int n8 = 0; n8 < 8; ++n8) {
                mma_tf32(acc[0][n8], a00, a01, a02, a03, b0a[n8], b1a[n8]);
                mma_tf32(acc[1][n8], a10, a11, a12, a13, b0a[n8], b1a[n8]);
            }
        }

        // ---- epilogue: gelu(h2) + layer3 + quad reduce + outputs ----
        const float2* w3e = (const float2*)sW3e;
        const float2* w3o = (const float2*)sW3o;
        #pragma unroll
        for (int mt = 0; mt < 2; ++mt) {
            #pragma unroll
            for (int half = 0; half < 2; ++half) {
                u64 lgP0 = pk2(0.f, 0.f), lgP1 = pk2(0.f, 0.f);
                #pragma unroll
                for (int n8 = 0; n8 < 8; ++n8) {
                    int j2 = n8 * 4 + qc;
                    u64 a = pk2(acc[mt][n8][2 * half], acc[mt][n8][2 * half + 1]);
                    u64 g = gelu2(a);
                    float2 we = w3e[j2], wo = w3o[j2];
                    lgP0 = ffma2(g, pk2(we.x, we.y), lgP0);
                    lgP1 = ffma2(g, pk2(wo.x, wo.y), lgP1);
                }
                float l0a, l0b, l1a, l1b;
                upk2(lgP0, l0a, l0b); upk2(lgP1, l1a, l1b);
                float lg0 = l0a + l0b, lg1 = l1a + l1b;
                lg0 += __shfl_xor_sync(0xffffffffu, lg0, 1);
                lg0 += __shfl_xor_sync(0xffffffffu, lg0, 2);
                lg1 += __shfl_xor_sync(0xffffffffu, lg1, 1);
                lg1 += __shfl_xor_sync(0xffffffffu, lg1, 2);

                if (qc == half + 2 * mt) {
                    int row = m0 + qr + 8 * half + 16 * mt;
                    int og  = tile * FTH + row;
                    lg0 += sCst[1]; lg1 += sCst[2];
                    float mxv = fmaxf(lg0, lg1);
                    float e0 = __expf(lg0 - mxv), e1 = __expf(lg1 - mxv);
                    float inv = __fdividef(1.0f, e0 + e1);
                    float g0 = e0 * inv, g1 = e1 * inv;
                    float xgr = sXg[row], xfr = sXf[row], mmr = sMm[row], xir = sXi[row];
                    float imputed  = fmaf(g0, xgr, g1 * xfr);
                    float complete = (mmr != 0.f) ? imputed : xir;
                    out_imp[og]  = imputed;
                    out_comp[og] = complete;
                    float2 gv; gv.x = g0; gv.y = g1;
                    *(float2*)(out_gate + (size_t)og * 2) = gv;
                }
            }
        }

        s = s_n; mm = mm_n; xf = xf_n; xi = xi_n;
    }
}

// ---------------------------------------------------------------------------
extern "C" void kernel_launch(void* const* d_in, const int* in_sizes, int n_in,
                              void* d_out, int out_size)
{
    const float* x     = (const float*)d_in[0];
    const float* mask  = (const float*)d_in[1];
    const int*   rid   = (const int*)  d_in[2];
    const float* emb   = (const float*)d_in[3];
    const float* gcw1  = (const float*)d_in[4];
    const float* gcb1  = (const float*)d_in[5];
    const float* gcw2  = (const float*)d_in[6];
    const float* gcb2  = (const float*)d_in[7];
    const float* fre   = (const float*)d_in[8];
    const float* fim   = (const float*)d_in[9];
    const float* rtab  = (const float*)d_in[10];
    const float* gw1   = (const float*)d_in[11];
    const float* gb1   = (const float*)d_in[12];
    const float* gw2   = (const float*)d_in[13];
    const float* gb2   = (const float*)d_in[14];
    const float* gw3   = (const float*)d_in[15];
    const float* gb3   = (const float*)d_in[16];
    float* out = (float*)d_out;

    cudaFuncSetAttribute(fused_kernel, cudaFuncAttributeMaxDynamicSharedMemorySize, SMEM_BYTES);

    adj_kernel<<<1, 64>>>(emb, rid, rtab, gw1, gb1, out + ADJ_OFF);
    fill_sum_kernel<<<256, 256>>>(x, mask);
    fill_scan_kernel<<<4, 256>>>();
    fill_out_kernel<<<256, 256>>>(x, mask, out + SEED_OFF);
    fft_kernel<<<B_ * N_ / 2, 256>>>(out + SEED_OFF, fre, fim, out + FREQ_OFF);
    fused_kernel<<<PGRID, FTH, SMEM_BYTES>>>(
        out + SEED_OFF, mask, x, out + FREQ_OFF,
        gw1, gw2, gb2, gw3, gb3,
        gcw1, gcb1, gcw2, gcb2,
        out + GCN_OFF, out + IMP_OFF, out + COMP_OFF, out + GATE_OFF);
}

// round 7
// speedup vs baseline: 1.0191x; 1.0191x over previous
#include <cuda_runtime.h>
#include <cuda_bf16.h>
#include <math.h>

#define B_ 16
#define T_ 2048
#define N_ 64

// Output layout (flattened tuple in order)
#define SEED_OFF 0
#define GCN_OFF  2097152
#define FREQ_OFF 4194304
#define IMP_OFF  6291456
#define COMP_OFF 8388608
#define GATE_OFF 10485760
#define ADJ_OFF  14680064

typedef unsigned long long u64;
typedef unsigned int u32;

// Scratch (static device arrays: allowed)
__device__ float  g_adj[N_ * N_];
__device__ float2 g_preb1p[32 * N_];
__device__ float  g_first[65536], g_last[65536];
__device__ unsigned char g_has[65536];
__device__ float  g_pref[65536], g_suf[65536];
__device__ unsigned char g_prefh[65536], g_sufh[65536];
__device__ float  g_seedT[B_ * N_ * T_];        // [b][n][t] transposed seed
__device__ float  g_freT[N_ * 1025];            // [n][k]
__device__ float  g_fimT[N_ * 1025];

// ---- packed f32x2 helpers ---------------------------------------------------
__device__ __forceinline__ u64 pk2(float lo, float hi) {
    u64 r; asm("mov.b64 %0, {%1, %2};" : "=l"(r) : "f"(lo), "f"(hi)); return r;
}
__device__ __forceinline__ void upk2(u64 v, float& lo, float& hi) {
    asm("mov.b64 {%0, %1}, %2;" : "=f"(lo), "=f"(hi) : "l"(v));
}
__device__ __forceinline__ u64 ffma2(u64 a, u64 b, u64 c) {
    u64 d; asm("fma.rn.f32x2 %0, %1, %2, %3;" : "=l"(d) : "l"(a), "l"(b), "l"(c)); return d;
}
__device__ __forceinline__ u64 mul2(u64 a, u64 b) {
    u64 d; asm("mul.rn.f32x2 %0, %1, %2;" : "=l"(d) : "l"(a), "l"(b)); return d;
}

__device__ __forceinline__ float tanh_ap(float x) {
    float t; asm("tanh.approx.f32 %0, %1;" : "=f"(t) : "f"(x)); return t;
}

// packed pairwise gelu: 5 packed fma-pipe ops + 2 MUFU
__device__ __forceinline__ u64 gelu2(u64 x) {
    const u64 C1 = pk2(0.035677408136f, 0.035677408136f);
    const u64 C0 = pk2(0.7978845608028654f, 0.7978845608028654f);
    const u64 H  = pk2(0.5f, 0.5f);
    u64 x2 = mul2(x, x);
    u64 inner = ffma2(x2, C1, C0);
    u64 b = mul2(x, inner);
    float b0, b1; upk2(b, b0, b1);
    u64 t = pk2(tanh_ap(b0), tanh_ap(b1));
    u64 hx = mul2(x, H);
    return ffma2(hx, t, hx);
}

__device__ __forceinline__ u32 to_tf32(float v) {
    u32 r; asm("cvt.rna.tf32.f32 %0, %1;" : "=r"(r) : "f"(v)); return r;
}

__device__ __forceinline__ void mma_tf32(float* d,
    u32 a0, u32 a1, u32 a2, u32 a3, u32 b0, u32 b1)
{
    asm("mma.sync.aligned.m16n8k8.row.col.f32.tf32.tf32.f32 "
        "{%0,%1,%2,%3}, {%4,%5,%6,%7}, {%8,%9}, {%0,%1,%2,%3};"
        : "+f"(d[0]), "+f"(d[1]), "+f"(d[2]), "+f"(d[3])
        : "r"(a0), "r"(a1), "r"(a2), "r"(a3), "r"(b0), "r"(b1));
}

// ---------------------------------------------------------------------------
// Fill stage 1
// ---------------------------------------------------------------------------
__global__ void __launch_bounds__(256) fill_sum_kernel(
    const float* __restrict__ x, const float* __restrict__ mask)
{
    int g = blockIdx.x * 256 + threadIdx.x;
    int n = g & 63;
    int c = (g >> 6) & 63;
    int b = g >> 12;
    int base = ((b * T_) + c * 32) * N_ + n;
    float first = 0.f, last = 0.f; bool has = false;
    #pragma unroll
    for (int t = 0; t < 32; ++t) {
        int idx = base + t * N_;
        float v = x[idx];
        bool obs = (mask[idx] == 0.f);
        if (obs) { if (!has) first = v; last = v; has = true; }
    }
    g_first[g] = first; g_last[g] = last; g_has[g] = (unsigned char)has;
}

// ---------------------------------------------------------------------------
// Fill stage 2
// ---------------------------------------------------------------------------
__global__ void __launch_bounds__(256) fill_scan_kernel()
{
    int g = blockIdx.x * 256 + threadIdx.x;
    int b = g >> 6, n = g & 63;
    int base = b * 4096 + n;
    float pv = 0.f; bool ph = false;
    #pragma unroll 8
    for (int c = 0; c < 64; ++c) {
        int i = base + c * 64;
        g_pref[i] = pv; g_prefh[i] = (unsigned char)ph;
        if (g_has[i]) { pv = g_last[i]; ph = true; }
    }
    float sv = 0.f; bool sh = false;
    #pragma unroll 8
    for (int c = 63; c >= 0; --c) {
        int i = base + c * 64;
        g_suf[i] = sv; g_sufh[i] = (unsigned char)sh;
        if (g_has[i]) { sv = g_first[i]; sh = true; }
    }
}

// ---------------------------------------------------------------------------
// Fill stage 3: writes seed (normal) + g_seedT (transposed, full-line stores)
// ---------------------------------------------------------------------------
__global__ void __launch_bounds__(256) fill_out_kernel(
    const float* __restrict__ x, const float* __restrict__ mask,
    float* __restrict__ seed)
{
    int g = blockIdx.x * 256 + threadIdx.x;
    int n = g & 63;
    int c = (g >> 6) & 63;
    int b = g >> 12;
    int base = ((b * T_) + c * 32) * N_ + n;
    float* tdst = g_seedT + ((size_t)(b * 64 + n)) * T_ + c * 32;

    float fv = g_pref[g]; bool fh = (bool)g_prefh[g];
    float vals[32];
    unsigned obsm = 0u, fam = 0u;
    #pragma unroll
    for (int t = 0; t < 32; ++t) {
        int idx = base + t * N_;
        float v = x[idx];
        bool obs = (mask[idx] == 0.f);
        if (obs) { fv = v; fh = true; obsm |= (1u << t); }
        vals[t] = fv;
        if (fh) fam |= (1u << t);
    }
    float bv = g_suf[g]; bool bh = (bool)g_sufh[g];
    #pragma unroll
    for (int t = 31; t >= 0; --t) {
        bool obs = (obsm >> t) & 1u;
        bool fa  = (fam  >> t) & 1u;
        float v = vals[t];
        if (obs) { bv = v; bh = true; }
        float out;
        if (obs)            out = v;
        else if (fa && bh)  out = 0.5f * (v + bv);
        else if (fa)        out = v;
        else if (bh)        out = bv;
        else                out = 0.f;
        seed[base + t * N_] = out;
        tdst[t] = out;
    }
}

// ---------------------------------------------------------------------------
// Filter transpose: freT[n][k] = fre[k][n]  (one-time, tiny)
// ---------------------------------------------------------------------------
__global__ void __launch_bounds__(256) filt_t_kernel(
    const float* __restrict__ fre, const float* __restrict__ fim)
{
    int n = blockIdx.x;
    for (int k = threadIdx.x; k < 1025; k += 256) {
        g_freT[n * 1025 + k] = fre[(size_t)k * N_ + n];
        g_fimT[n * 1025 + k] = fim[(size_t)k * N_ + n];
    }
}

// ---------------------------------------------------------------------------
// Kernel 2: adjacency + rate-embed pre-bias
// ---------------------------------------------------------------------------
__global__ void __launch_bounds__(64) adj_kernel(
    const float* __restrict__ emb, const int* __restrict__ rate_id,
    const float* __restrict__ rate_table, const float* __restrict__ gw1,
    const float* __restrict__ gb1, float* __restrict__ out_adj)
{
    __shared__ float sE[64 * 32];
    int tid = threadIdx.x;
    for (int i = tid; i < 64 * 32; i += 64) sE[i] = emb[i];
    __syncthreads();

    float sc[64];
    float mx = -1e30f;
    #pragma unroll
    for (int m = 0; m < 64; ++m) {
        float d = 0.f;
        #pragma unroll
        for (int h = 0; h < 32; ++h) d = fmaf(sE[tid * 32 + h], sE[m * 32 + h], d);
        d = fmaxf(d, 0.f);
        sc[m] = d; mx = fmaxf(mx, d);
    }
    float sum = 0.f;
    #pragma unroll
    for (int m = 0; m < 64; ++m) { float e = __expf(sc[m] - mx); sc[m] = e; sum += e; }
    float inv = 1.0f / sum;
    #pragma unroll
    for (int m = 0; m < 64; ++m) {
        float a = sc[m] * inv;
        g_adj[tid * 64 + m] = a;
        out_adj[tid * 64 + m] = a;
    }
    int rid = rate_id[tid];
    for (int j2 = 0; j2 < 32; ++j2) {
        float v0 = gb1[2 * j2], v1 = gb1[2 * j2 + 1];
        #pragma unroll
        for (int e = 0; e < 16; ++e) {
            float rt = rate_table[rid * 16 + e];
            v0 = fmaf(rt, gw1[(6 + e) * 64 + 2 * j2], v0);
            v1 = fmaf(rt, gw1[(6 + e) * 64 + 2 * j2 + 1], v1);
        }
        g_preb1p[j2 * 64 + tid] = make_float2(v0, v1);
    }
}

// ---------------------------------------------------------------------------
// Kernel 3: packed-pair radix-2 FFT filter; coalesced loads from g_seedT
// and g_freT/g_fimT. Output store unchanged (strided float2).
// ---------------------------------------------------------------------------
__global__ void __launch_bounds__(256) fft_kernel(
    float* __restrict__ xfreq)
{
    __shared__ float re[2048], im[2048], twr[1024], twi[1024];
    int tid = threadIdx.x;
    int b = blockIdx.x >> 5;
    int p = blockIdx.x & 31;
    int n0 = p * 2;
    const float* src0 = g_seedT + ((size_t)(b * 64 + n0)) * T_;
    const float* src1 = src0 + T_;

    for (int j = tid; j < 1024; j += 256) {
        float s, c;
        sincosf(-6.28318530717958647692f * (float)j * (1.0f / 2048.0f), &s, &c);
        twr[j] = c; twi[j] = s;
    }
    for (int t = tid; t < 2048; t += 256) {
        re[t] = src0[t];
        im[t] = src1[t];
    }

    for (int s = 10; s >= 0; --s) {
        int half = 1 << s;
        __syncthreads();
        for (int bi = tid; bi < 1024; bi += 256) {
            int j = bi & (half - 1);
            int i1 = ((bi >> s) << (s + 1)) | j;
            int i2 = i1 + half;
            int tj = j << (10 - s);
            float wr = twr[tj], wi = twi[tj];
            float ar = re[i1], ai = im[i1], br = re[i2], b2 = im[i2];
            re[i1] = ar + br; im[i1] = ai + b2;
            float dr = ar - br, di = ai - b2;
            re[i2] = dr * wr - di * wi;
            im[i2] = dr * wi + di * wr;
        }
    }
    __syncthreads();

    const float* fT0r = g_freT + n0 * 1025;
    const float* fT0i = g_fimT + n0 * 1025;
    const float* fT1r = fT0r + 1025;
    const float* fT1i = fT0i + 1025;
    for (int k = tid; k <= 1024; k += 256) {
        int km = (2048 - k) & 2047;
        int pk = __brev(k) >> 21;
        int pm = __brev(km) >> 21;
        float zr = re[pk], zi = im[pk];
        float yr = re[pm], yi = im[pm];
        float x1r = 0.5f * (zr + yr), x1i = 0.5f * (zi - yi);
        float x2r = 0.5f * (zi + yi), x2i = 0.5f * (yr - zr);
        float h1r = fT0r[k], h1i = fT0i[k];
        float h2r = fT1r[k], h2i = fT1i[k];
        float y1r = x1r * h1r - x1i * h1i, y1i = x1r * h1i + x1i * h1r;
        float y2r = x2r * h2r - x2i * h2i, y2i = x2r * h2i + x2i * h2r;
        if (k == 0 || k == 1024) { y1i = 0.f; y2i = 0.f; }
        re[pk] = y1r - y2i; im[pk] = y1i + y2r;
        if (k > 0 && k < 1024) { re[pm] = y1r + y2i; im[pm] = y2r - y1i; }
    }

    for (int s = 0; s <= 10; ++s) {
        int half = 1 << s;
        __syncthreads();
        for (int bi = tid; bi < 1024; bi += 256) {
            int j = bi & (half - 1);
            int i1 = ((bi >> s) << (s + 1)) | j;
            int i2 = i1 + half;
            int tj = j << (10 - s);
            float wr = twr[tj], wi = -twi[tj];
            float br = re[i2], b2 = im[i2];
            float tr = br * wr - b2 * wi, ti = br * wi + b2 * wr;
            float ar = re[i1], ai = im[i1];
            re[i1] = ar + tr; im[i1] = ai + ti;
            re[i2] = ar - tr; im[i2] = ai - ti;
        }
    }
    __syncthreads();

    float* dst = xfreq + (size_t)b * T_ * N_ + n0;
    const float scl = 1.0f / 2048.0f;
    for (int t = tid; t < 2048; t += 256) {
        float2 v; v.x = re[t] * scl; v.y = im[t] * scl;
        *(float2*)(dst + (size_t)t * N_) = v;
    }
}

// ---------------------------------------------------------------------------
// Kernel 4 (R5 layout + u64 W1 loads): persistent; tf32 mma layer2.
// ---------------------------------------------------------------------------
#define FTH 512
#define HS_S 520
#define W2_S 72
#define NTILES (B_ * T_ * N_ / FTH)   // 4096
#define PGRID 148
#define SMEM_BYTES (49444 * 4)

__global__ void __launch_bounds__(FTH, 1) fused_kernel(
    const float* __restrict__ seed, const float* __restrict__ mask,
    const float* __restrict__ xin, const float* __restrict__ xfreq,
    const float* __restrict__ gw1, const float* __restrict__ gw2,
    const float* __restrict__ gb2, const float* __restrict__ gw3,
    const float* __restrict__ gb3,
    const float* __restrict__ gcw1, const float* __restrict__ gcb1,
    const float* __restrict__ gcw2, const float* __restrict__ gcb2,
    float* __restrict__ out_gcn, float* __restrict__ out_imp,
    float* __restrict__ out_comp, float* __restrict__ out_gate)
{
    extern __shared__ float sm[];
    float* hs    = sm;                    // [64][520] (tf32 bits)
    float* sW2   = hs    + 64 * HS_S;     // [64][72] (tf32 bits)
    float* sA    = sW2   + 64 * W2_S;     // [64][66]
    float* sPreb = sA    + 64 * 66;       // [32][64] float2
    float* sW1   = sPreb + 4096;          // [6][64]
    float* sW3e  = sW1   + 384;           // [32] float2
    float* sW3o  = sW3e  + 64;            // [32] float2
    float* sB2   = sW3o  + 64;            // [64]
    float* sGc   = sB2   + 64;            // [96]
    float* sPm   = sGc   + 96;            // [8][64]
    float* sXg   = sPm   + FTH;
    float* sXf   = sXg   + FTH;
    float* sMm   = sXf   + FTH;
    float* sXi   = sMm   + FTH;
    float* sCst  = sXi   + FTH;           // [4]

    int tid = threadIdx.x;

    // ---- stage weights once ----
    for (int i = tid; i < 4096; i += FTH) {
        int k = i >> 6, j = i & 63;
        ((u32*)sW2)[k * W2_S + j] = to_tf32(gw2[i]);
    }
    for (int i = tid; i < 4096; i += FTH) sA[(i >> 6) * 66 + (i & 63)] = g_adj[i];
    for (int i = tid; i < 2048; i += FTH) ((float2*)sPreb)[i] = g_preb1p[i];
    if (tid < 384) sW1[tid] = gw1[tid];
    if (tid < 32) {
        ((float2*)sW3e)[tid] = make_float2(gw3[4 * tid],     gw3[4 * tid + 2]);
        ((float2*)sW3o)[tid] = make_float2(gw3[4 * tid + 1], gw3[4 * tid + 3]);
        sGc[tid] = gcw1[tid]; sGc[32 + tid] = gcb1[tid]; sGc[64 + tid] = gcw2[tid];
    }
    if (tid < 64) sB2[tid] = gb2[tid];
    if (tid == 0) { sCst[0] = gcb2[0]; sCst[1] = gb3[0]; sCst[2] = gb3[1]; }

    int n    = tid & 63;
    int r    = tid >> 6;      // 0..7
    int lane = tid & 31;
    int warp = tid >> 5;      // 0..15
    int m0   = warp * 32;
    int qr   = lane >> 2;     // quad row 0..7
    int qc   = lane & 3;      // quad col 0..3

    for (int tile = blockIdx.x; tile < NTILES; tile += PGRID) {
        __syncthreads();

        int gidx = tile * FTH + tid;
        float s  = seed[gidx];
        float mm = mask[gidx];
        float xf = xfreq[gidx];
        float xi = xin[gidx];

        // ---- phi(s), packed pairs ----
        u64 sp = pk2(s, s);
        u64 accp = pk2(0.f, 0.f);
        const u64* gcW = (const u64*)sGc;
        const u64* gcB = (const u64*)(sGc + 32);
        const u64* gcV = (const u64*)(sGc + 64);
        #pragma unroll
        for (int hq = 0; hq < 16; ++hq) {
            u64 pre = ffma2(sp, gcW[hq], gcB[hq]);
            accp = ffma2(gelu2(pre), gcV[hq], accp);
        }
        float p0, p1; upk2(accp, p0, p1);
        sPm[r * 64 + n] = p0 + p1;
        __syncthreads();

        // ---- x_gcn (packed matvec) ----
        u64 xgp = pk2(0.f, 0.f);
        const u64* arow = (const u64*)(sA + n * 66);
        const u64* prow = (const u64*)(sPm + r * 64);
        #pragma unroll 8
        for (int m2 = 0; m2 < 32; ++m2)
            xgp = ffma2(arow[m2], prow[m2], xgp);
        float xg0, xg1; upk2(xgp, xg0, xg1);
        float xg = xg0 + xg1 + sCst[0];

        sXg[tid] = xg; sXf[tid] = xf; sMm[tid] = mm; sXi[tid] = xi;
        out_gcn[gidx] = xg;

        // ---- layer1 (packed, u64 weight loads) -> hs as tf32 ----
        u64 u0 = pk2(s, s), u1 = pk2(mm, mm), u2 = pk2(xg, xg);
        u64 u3 = pk2(xf, xf), u4 = pk2(xg - s, xg - s), u5 = pk2(xf - s, xf - s);
        const u64* W1p = (const u64*)sW1;             // [6][32] pairs
        const u64* prebp = (const u64*)sPreb;
        u32* hsu = (u32*)hs;
        #pragma unroll
        for (int jq = 0; jq < 16; ++jq) {
            u64 a0 = prebp[(2 * jq) * 64 + n];
            u64 a1 = prebp[(2 * jq + 1) * 64 + n];
            int p2 = jq * 2;
            a0 = ffma2(u0, W1p[0 * 32 + p2], a0); a1 = ffma2(u0, W1p[0 * 32 + p2 + 1], a1);
            a0 = ffma2(u1, W1p[1 * 32 + p2], a0); a1 = ffma2(u1, W1p[1 * 32 + p2 + 1], a1);
            a0 = ffma2(u2, W1p[2 * 32 + p2], a0); a1 = ffma2(u2, W1p[2 * 32 + p2 + 1], a1);
            a0 = ffma2(u3, W1p[3 * 32 + p2], a0); a1 = ffma2(u3, W1p[3 * 32 + p2 + 1], a1);
            a0 = ffma2(u4, W1p[4 * 32 + p2], a0); a1 = ffma2(u4, W1p[4 * 32 + p2 + 1], a1);
            a0 = ffma2(u5, W1p[5 * 32 + p2], a0); a1 = ffma2(u5, W1p[5 * 32 + p2 + 1], a1);
            u64 g0 = gelu2(a0);
            u64 g1 = gelu2(a1);
            float v0, v1, v2, v3;
            upk2(g0, v0, v1); upk2(g1, v2, v3);
            hsu[(4 * jq + 0) * HS_S + tid] = to_tf32(v0);
            hsu[(4 * jq + 1) * HS_S + tid] = to_tf32(v1);
            hsu[(4 * jq + 2) * HS_S + tid] = to_tf32(v2);
            hsu[(4 * jq + 3) * HS_S + tid] = to_tf32(v3);
        }
        __syncthreads();

        // ---- Phase B: layer2 via tf32 mma (R5 layout) ----
        float acc[2][8][4];
        #pragma unroll
        for (int n8 = 0; n8 < 8; ++n8) {
            int j0 = n8 * 8 + qc * 2;
            float2 bb = *(const float2*)(sB2 + j0);
            #pragma unroll
            for (int mt = 0; mt < 2; ++mt) {
                acc[mt][n8][0] = bb.x; acc[mt][n8][1] = bb.y;
                acc[mt][n8][2] = bb.x; acc[mt][n8][3] = bb.y;
            }
        }

        const u32* hsub = (const u32*)hs;
        const u32* w2u  = (const u32*)sW2;
        int ar = m0 + qr;
        #pragma unroll
        for (int k8 = 0; k8 < 8; ++k8) {
            int kb = k8 * 8 + qc;
            const u32* h0 = hsub + kb * HS_S;
            const u32* h4 = hsub + (kb + 4) * HS_S;
            u32 a00 = h0[ar],      a01 = h0[ar + 8],  a02 = h4[ar],      a03 = h4[ar + 8];
            u32 a10 = h0[ar + 16], a11 = h0[ar + 24], a12 = h4[ar + 16], a13 = h4[ar + 24];
            const u32* b0p = w2u + kb * W2_S + qr;
            const u32* b1p = w2u + (kb + 4) * W2_S + qr;
            #pragma unroll
            for (int n8 = 0; n8 < 8; ++n8) {
                u32 b0 = b0p[n8 * 8];
                u32 b1 = b1p[n8 * 8];
                mma_tf32(acc[0][n8], a00, a01, a02, a03, b0, b1);
                mma_tf32(acc[1][n8], a10, a11, a12, a13, b0, b1);
            }
        }

        // ---- epilogue: gelu(h2) + layer3 + quad reduce + outputs ----
        const float2* w3e = (const float2*)sW3e;
        const float2* w3o = (const float2*)sW3o;
        #pragma unroll
        for (int mt = 0; mt < 2; ++mt) {
            #pragma unroll
            for (int half = 0; half < 2; ++half) {
                u64 lgP0 = pk2(0.f, 0.f), lgP1 = pk2(0.f, 0.f);
                #pragma unroll
                for (int n8 = 0; n8 < 8; ++n8) {
                    int j2 = n8 * 4 + qc;
                    u64 a = pk2(acc[mt][n8][2 * half], acc[mt][n8][2 * half + 1]);
                    u64 g = gelu2(a);
                    float2 we = w3e[j2], wo = w3o[j2];
                    lgP0 = ffma2(g, pk2(we.x, we.y), lgP0);
                    lgP1 = ffma2(g, pk2(wo.x, wo.y), lgP1);
                }
                float l0a, l0b, l1a, l1b;
                upk2(lgP0, l0a, l0b); upk2(lgP1, l1a, l1b);
                float lg0 = l0a + l0b, lg1 = l1a + l1b;
                lg0 += __shfl_xor_sync(0xffffffffu, lg0, 1);
                lg0 += __shfl_xor_sync(0xffffffffu, lg0, 2);
                lg1 += __shfl_xor_sync(0xffffffffu, lg1, 1);
                lg1 += __shfl_xor_sync(0xffffffffu, lg1, 2);

                if (qc == half + 2 * mt) {
                    int row = m0 + qr + 8 * half + 16 * mt;
                    int og  = tile * FTH + row;
                    lg0 += sCst[1]; lg1 += sCst[2];
                    float mxv = fmaxf(lg0, lg1);
                    float e0 = __expf(lg0 - mxv), e1 = __expf(lg1 - mxv);
                    float inv = __fdividef(1.0f, e0 + e1);
                    float g0 = e0 * inv, g1 = e1 * inv;
                    float xgr = sXg[row], xfr = sXf[row], mmr = sMm[row], xir = sXi[row];
                    float imputed  = fmaf(g0, xgr, g1 * xfr);
                    float complete = (mmr != 0.f) ? imputed : xir;
                    out_imp[og]  = imputed;
                    out_comp[og] = complete;
                    float2 gv; gv.x = g0; gv.y = g1;
                    *(float2*)(out_gate + (size_t)og * 2) = gv;
                }
            }
        }
    }
}

// ---------------------------------------------------------------------------
extern "C" void kernel_launch(void* const* d_in, const int* in_sizes, int n_in,
                              void* d_out, int out_size)
{
    const float* x     = (const float*)d_in[0];
    const float* mask  = (const float*)d_in[1];
    const int*   rid   = (const int*)  d_in[2];
    const float* emb   = (const float*)d_in[3];
    const float* gcw1  = (const float*)d_in[4];
    const float* gcb1  = (const float*)d_in[5];
    const float* gcw2  = (const float*)d_in[6];
    const float* gcb2  = (const float*)d_in[7];
    const float* fre   = (const float*)d_in[8];
    const float* fim   = (const float*)d_in[9];
    const float* rtab  = (const float*)d_in[10];
    const float* gw1   = (const float*)d_in[11];
    const float* gb1   = (const float*)d_in[12];
    const float* gw2   = (const float*)d_in[13];
    const float* gb2   = (const float*)d_in[14];
    const float* gw3   = (const float*)d_in[15];
    const float* gb3   = (const float*)d_in[16];
    float* out = (float*)d_out;

    cudaFuncSetAttribute(fused_kernel, cudaFuncAttributeMaxDynamicSharedMemorySize, SMEM_BYTES);

    adj_kernel<<<1, 64>>>(emb, rid, rtab, gw1, gb1, out + ADJ_OFF);
    filt_t_kernel<<<64, 256>>>(fre, fim);
    fill_sum_kernel<<<256, 256>>>(x, mask);
    fill_scan_kernel<<<4, 256>>>();
    fill_out_kernel<<<256, 256>>>(x, mask, out + SEED_OFF);
    fft_kernel<<<B_ * N_ / 2, 256>>>(out + FREQ_OFF);
    fused_kernel<<<PGRID, FTH, SMEM_BYTES>>>(
        out + SEED_OFF, mask, x, out + FREQ_OFF,
        gw1, gw2, gb2, gw3, gb3,
        gcw1, gcb1, gcw2, gcb2,
        out + GCN_OFF, out + IMP_OFF, out + COMP_OFF, out + GATE_OFF);
}

// round 8
// speedup vs baseline: 1.1348x; 1.1135x over previous
#include <cuda_runtime.h>
#include <cuda_bf16.h>
#include <math.h>

#define B_ 16
#define T_ 2048
#define N_ 64

// Output layout (flattened tuple in order)
#define SEED_OFF 0
#define GCN_OFF  2097152
#define FREQ_OFF 4194304
#define IMP_OFF  6291456
#define COMP_OFF 8388608
#define GATE_OFF 10485760
#define ADJ_OFF  14680064

typedef unsigned long long u64;
typedef unsigned int u32;

// Scratch (static device arrays: allowed)
// Chunk-summary scratch is laid out TRANSPOSED: s = (b*64 + n)*64 + c
__device__ float  g_adj[N_ * N_];
__device__ float2 g_preb1p[32 * N_];
__device__ float  g_first[65536], g_last[65536];
__device__ unsigned char g_has[65536];
__device__ float  g_pref[65536], g_suf[65536];
__device__ unsigned char g_prefh[65536], g_sufh[65536];
__device__ float  g_seedT[B_ * N_ * T_];        // [b][n][t] transposed seed
__device__ float  g_freT[N_ * 1025];            // [n][k]
__device__ float  g_fimT[N_ * 1025];

// ---- packed f32x2 helpers ---------------------------------------------------
__device__ __forceinline__ u64 pk2(float lo, float hi) {
    u64 r; asm("mov.b64 %0, {%1, %2};" : "=l"(r) : "f"(lo), "f"(hi)); return r;
}
__device__ __forceinline__ void upk2(u64 v, float& lo, float& hi) {
    asm("mov.b64 {%0, %1}, %2;" : "=f"(lo), "=f"(hi) : "l"(v));
}
__device__ __forceinline__ u64 ffma2(u64 a, u64 b, u64 c) {
    u64 d; asm("fma.rn.f32x2 %0, %1, %2, %3;" : "=l"(d) : "l"(a), "l"(b), "l"(c)); return d;
}
__device__ __forceinline__ u64 mul2(u64 a, u64 b) {
    u64 d; asm("mul.rn.f32x2 %0, %1, %2;" : "=l"(d) : "l"(a), "l"(b)); return d;
}

__device__ __forceinline__ float tanh_ap(float x) {
    float t; asm("tanh.approx.f32 %0, %1;" : "=f"(t) : "f"(x)); return t;
}

// packed pairwise gelu: 5 packed fma-pipe ops + 2 MUFU
__device__ __forceinline__ u64 gelu2(u64 x) {
    const u64 C1 = pk2(0.035677408136f, 0.035677408136f);
    const u64 C0 = pk2(0.7978845608028654f, 0.7978845608028654f);
    const u64 H  = pk2(0.5f, 0.5f);
    u64 x2 = mul2(x, x);
    u64 inner = ffma2(x2, C1, C0);
    u64 b = mul2(x, inner);
    float b0, b1; upk2(b, b0, b1);
    u64 t = pk2(tanh_ap(b0), tanh_ap(b1));
    u64 hx = mul2(x, H);
    return ffma2(hx, t, hx);
}

__device__ __forceinline__ u32 to_tf32(float v) {
    u32 r; asm("cvt.rna.tf32.f32 %0, %1;" : "=r"(r) : "f"(v)); return r;
}

__device__ __forceinline__ void mma_tf32(float* d,
    u32 a0, u32 a1, u32 a2, u32 a3, u32 b0, u32 b1)
{
    asm("mma.sync.aligned.m16n8k8.row.col.f32.tf32.tf32.f32 "
        "{%0,%1,%2,%3}, {%4,%5,%6,%7}, {%8,%9}, {%0,%1,%2,%3};"
        : "+f"(d[0]), "+f"(d[1]), "+f"(d[2]), "+f"(d[3])
        : "r"(a0), "r"(a1), "r"(a2), "r"(a3), "r"(b0), "r"(b1));
}

// ---------------------------------------------------------------------------
// Fill stage 1: 32-step chunk summaries -> transposed scratch (b,n,c)
// ---------------------------------------------------------------------------
__global__ void __launch_bounds__(256) fill_sum_kernel(
    const float* __restrict__ x, const float* __restrict__ mask)
{
    int g = blockIdx.x * 256 + threadIdx.x;
    int n = g & 63;
    int c = (g >> 6) & 63;
    int b = g >> 12;
    int base = ((b * T_) + c * 32) * N_ + n;
    float first = 0.f, last = 0.f; bool has = false;
    #pragma unroll
    for (int t = 0; t < 32; ++t) {
        int idx = base + t * N_;
        float v = x[idx];
        bool obs = (mask[idx] == 0.f);
        if (obs) { if (!has) first = v; last = v; has = true; }
    }
    int s = ((b << 6) + n) * 64 + c;    // transposed
    g_first[s] = first; g_last[s] = last; g_has[s] = (unsigned char)has;
}

// ---------------------------------------------------------------------------
// Fill stage 2: per-(b,n) scan over 64 contiguous chunks, registers only.
// grid 8 x 128 threads = 1024 scans.
// ---------------------------------------------------------------------------
__global__ void __launch_bounds__(128) fill_scan_kernel()
{
    int g = blockIdx.x * 128 + threadIdx.x;   // 0..1023 == (b*64+n)
    int base = g * 64;

    float fi[64], la[64];
    unsigned char ha[64];
    #pragma unroll
    for (int q = 0; q < 16; ++q) {
        *(float4*)(fi + q * 4) = *(const float4*)(g_first + base + q * 4);
        *(float4*)(la + q * 4) = *(const float4*)(g_last + base + q * 4);
    }
    #pragma unroll
    for (int q = 0; q < 4; ++q)
        *(uint4*)(ha + q * 16) = *(const uint4*)(g_has + base + q * 16);

    float pr[64], su[64];
    unsigned char prh[64], suh[64];
    float pv = 0.f; bool ph = false;
    #pragma unroll
    for (int c = 0; c < 64; ++c) {
        pr[c] = pv; prh[c] = (unsigned char)ph;
        if (ha[c]) { pv = la[c]; ph = true; }
    }
    float sv = 0.f; bool sh = false;
    #pragma unroll
    for (int c = 63; c >= 0; --c) {
        su[c] = sv; suh[c] = (unsigned char)sh;
        if (ha[c]) { sv = fi[c]; sh = true; }
    }

    #pragma unroll
    for (int q = 0; q < 16; ++q) {
        *(float4*)(g_pref + base + q * 4) = *(const float4*)(pr + q * 4);
        *(float4*)(g_suf  + base + q * 4) = *(const float4*)(su + q * 4);
    }
    #pragma unroll
    for (int q = 0; q < 4; ++q) {
        *(uint4*)(g_prefh + base + q * 16) = *(const uint4*)(prh + q * 16);
        *(uint4*)(g_sufh  + base + q * 16) = *(const uint4*)(suh + q * 16);
    }
}

// ---------------------------------------------------------------------------
// Fill stage 3: writes seed (normal) + g_seedT (transposed)
// ---------------------------------------------------------------------------
__global__ void __launch_bounds__(256) fill_out_kernel(
    const float* __restrict__ x, const float* __restrict__ mask,
    float* __restrict__ seed)
{
    int g = blockIdx.x * 256 + threadIdx.x;
    int n = g & 63;
    int c = (g >> 6) & 63;
    int b = g >> 12;
    int base = ((b * T_) + c * 32) * N_ + n;
    int s = ((b << 6) + n) * 64 + c;    // transposed scratch index
    float* tdst = g_seedT + ((size_t)(b * 64 + n)) * T_ + c * 32;

    float fv = g_pref[s]; bool fh = (bool)g_prefh[s];
    float vals[32];
    unsigned obsm = 0u, fam = 0u;
    #pragma unroll
    for (int t = 0; t < 32; ++t) {
        int idx = base + t * N_;
        float v = x[idx];
        bool obs = (mask[idx] == 0.f);
        if (obs) { fv = v; fh = true; obsm |= (1u << t); }
        vals[t] = fv;
        if (fh) fam |= (1u << t);
    }
    float bv = g_suf[s]; bool bh = (bool)g_sufh[s];
    #pragma unroll
    for (int t = 31; t >= 0; --t) {
        bool obs = (obsm >> t) & 1u;
        bool fa  = (fam  >> t) & 1u;
        float v = vals[t];
        if (obs) { bv = v; bh = true; }
        float out;
        if (obs)            out = v;
        else if (fa && bh)  out = 0.5f * (v + bv);
        else if (fa)        out = v;
        else if (bh)        out = bv;
        else                out = 0.f;
        seed[base + t * N_] = out;
        tdst[t] = out;
    }
}

// ---------------------------------------------------------------------------
// Filter transpose: freT[n][k] = fre[k][n]  (one-time, tiny)
// ---------------------------------------------------------------------------
__global__ void __launch_bounds__(256) filt_t_kernel(
    const float* __restrict__ fre, const float* __restrict__ fim)
{
    int n = blockIdx.x;
    for (int k = threadIdx.x; k < 1025; k += 256) {
        g_freT[n * 1025 + k] = fre[(size_t)k * N_ + n];
        g_fimT[n * 1025 + k] = fim[(size_t)k * N_ + n];
    }
}

// ---------------------------------------------------------------------------
// Kernel 2: adjacency + rate-embed pre-bias
// ---------------------------------------------------------------------------
__global__ void __launch_bounds__(64) adj_kernel(
    const float* __restrict__ emb, const int* __restrict__ rate_id,
    const float* __restrict__ rate_table, const float* __restrict__ gw1,
    const float* __restrict__ gb1, float* __restrict__ out_adj)
{
    __shared__ float sE[64 * 32];
    int tid = threadIdx.x;
    for (int i = tid; i < 64 * 32; i += 64) sE[i] = emb[i];
    __syncthreads();

    float sc[64];
    float mx = -1e30f;
    #pragma unroll
    for (int m = 0; m < 64; ++m) {
        float d = 0.f;
        #pragma unroll
        for (int h = 0; h < 32; ++h) d = fmaf(sE[tid * 32 + h], sE[m * 32 + h], d);
        d = fmaxf(d, 0.f);
        sc[m] = d; mx = fmaxf(mx, d);
    }
    float sum = 0.f;
    #pragma unroll
    for (int m = 0; m < 64; ++m) { float e = __expf(sc[m] - mx); sc[m] = e; sum += e; }
    float inv = 1.0f / sum;
    #pragma unroll
    for (int m = 0; m < 64; ++m) {
        float a = sc[m] * inv;
        g_adj[tid * 64 + m] = a;
        out_adj[tid * 64 + m] = a;
    }
    int rid = rate_id[tid];
    for (int j2 = 0; j2 < 32; ++j2) {
        float v0 = gb1[2 * j2], v1 = gb1[2 * j2 + 1];
        #pragma unroll
        for (int e = 0; e < 16; ++e) {
            float rt = rate_table[rid * 16 + e];
            v0 = fmaf(rt, gw1[(6 + e) * 64 + 2 * j2], v0);
            v1 = fmaf(rt, gw1[(6 + e) * 64 + 2 * j2 + 1], v1);
        }
        g_preb1p[j2 * 64 + tid] = make_float2(v0, v1);
    }
}

// ---------------------------------------------------------------------------
// Kernel 3: packed-pair radix-2 FFT filter; coalesced loads
// ---------------------------------------------------------------------------
__global__ void __launch_bounds__(256) fft_kernel(
    float* __restrict__ xfreq)
{
    __shared__ float re[2048], im[2048], twr[1024], twi[1024];
    int tid = threadIdx.x;
    int b = blockIdx.x >> 5;
    int p = blockIdx.x & 31;
    int n0 = p * 2;
    const float* src0 = g_seedT + ((size_t)(b * 64 + n0)) * T_;
    const float* src1 = src0 + T_;

    for (int j = tid; j < 1024; j += 256) {
        float s, c;
        sincosf(-6.28318530717958647692f * (float)j * (1.0f / 2048.0f), &s, &c);
        twr[j] = c; twi[j] = s;
    }
    for (int t = tid; t < 2048; t += 256) {
        re[t] = src0[t];
        im[t] = src1[t];
    }

    for (int s = 10; s >= 0; --s) {
        int half = 1 << s;
        __syncthreads();
        for (int bi = tid; bi < 1024; bi += 256) {
            int j = bi & (half - 1);
            int i1 = ((bi >> s) << (s + 1)) | j;
            int i2 = i1 + half;
            int tj = j << (10 - s);
            float wr = twr[tj], wi = twi[tj];
            float ar = re[i1], ai = im[i1], br = re[i2], b2 = im[i2];
            re[i1] = ar + br; im[i1] = ai + b2;
            float dr = ar - br, di = ai - b2;
            re[i2] = dr * wr - di * wi;
            im[i2] = dr * wi + di * wr;
        }
    }
    __syncthreads();

    const float* fT0r = g_freT + n0 * 1025;
    const float* fT0i = g_fimT + n0 * 1025;
    const float* fT1r = fT0r + 1025;
    const float* fT1i = fT0i + 1025;
    for (int k = tid; k <= 1024; k += 256) {
        int km = (2048 - k) & 2047;
        int pk = __brev(k) >> 21;
        int pm = __brev(km) >> 21;
        float zr = re[pk], zi = im[pk];
        float yr = re[pm], yi = im[pm];
        float x1r = 0.5f * (zr + yr), x1i = 0.5f * (zi - yi);
        float x2r = 0.5f * (zi + yi), x2i = 0.5f * (yr - zr);
        float h1r = fT0r[k], h1i = fT0i[k];
        float h2r = fT1r[k], h2i = fT1i[k];
        float y1r = x1r * h1r - x1i * h1i, y1i = x1r * h1i + x1i * h1r;
        float y2r = x2r * h2r - x2i * h2i, y2i = x2r * h2i + x2i * h2r;
        if (k == 0 || k == 1024) { y1i = 0.f; y2i = 0.f; }
        re[pk] = y1r - y2i; im[pk] = y1i + y2r;
        if (k > 0 && k < 1024) { re[pm] = y1r + y2i; im[pm] = y2r - y1i; }
    }

    for (int s = 0; s <= 10; ++s) {
        int half = 1 << s;
        __syncthreads();
        for (int bi = tid; bi < 1024; bi += 256) {
            int j = bi & (half - 1);
            int i1 = ((bi >> s) << (s + 1)) | j;
            int i2 = i1 + half;
            int tj = j << (10 - s);
            float wr = twr[tj], wi = -twi[tj];
            float br = re[i2], b2 = im[i2];
            float tr = br * wr - b2 * wi, ti = br * wi + b2 * wr;
            float ar = re[i1], ai = im[i1];
            re[i1] = ar + tr; im[i1] = ai + ti;
            re[i2] = ar - tr; im[i2] = ai - ti;
        }
    }
    __syncthreads();

    float* dst = xfreq + (size_t)b * T_ * N_ + n0;
    const float scl = 1.0f / 2048.0f;
    for (int t = tid; t < 2048; t += 256) {
        float2 v; v.x = re[t] * scl; v.y = im[t] * scl;
        *(float2*)(dst + (size_t)t * N_) = v;
    }
}

// ---------------------------------------------------------------------------
// Kernel 4 (R5 layout + u64 W1 loads): persistent; tf32 mma layer2.
// ---------------------------------------------------------------------------
#define FTH 512
#define HS_S 520
#define W2_S 72
#define NTILES (B_ * T_ * N_ / FTH)   // 4096
#define PGRID 148
#define SMEM_BYTES (49444 * 4)

__global__ void __launch_bounds__(FTH, 1) fused_kernel(
    const float* __restrict__ seed, const float* __restrict__ mask,
    const float* __restrict__ xin, const float* __restrict__ xfreq,
    const float* __restrict__ gw1, const float* __restrict__ gw2,
    const float* __restrict__ gb2, const float* __restrict__ gw3,
    const float* __restrict__ gb3,
    const float* __restrict__ gcw1, const float* __restrict__ gcb1,
    const float* __restrict__ gcw2, const float* __restrict__ gcb2,
    float* __restrict__ out_gcn, float* __restrict__ out_imp,
    float* __restrict__ out_comp, float* __restrict__ out_gate)
{
    extern __shared__ float sm[];
    float* hs    = sm;                    // [64][520] (tf32 bits)
    float* sW2   = hs    + 64 * HS_S;     // [64][72] (tf32 bits)
    float* sA    = sW2   + 64 * W2_S;     // [64][66]
    float* sPreb = sA    + 64 * 66;       // [32][64] float2
    float* sW1   = sPreb + 4096;          // [6][64]
    float* sW3e  = sW1   + 384;           // [32] float2
    float* sW3o  = sW3e  + 64;            // [32] float2
    float* sB2   = sW3o  + 64;            // [64]
    float* sGc   = sB2   + 64;            // [96]
    float* sPm   = sGc   + 96;            // [8][64]
    float* sXg   = sPm   + FTH;
    float* sXf   = sXg   + FTH;
    float* sMm   = sXf   + FTH;
    float* sXi   = sMm   + FTH;
    float* sCst  = sXi   + FTH;           // [4]

    int tid = threadIdx.x;

    // ---- stage weights once ----
    for (int i = tid; i < 4096; i += FTH) {
        int k = i >> 6, j = i & 63;
        ((u32*)sW2)[k * W2_S + j] = to_tf32(gw2[i]);
    }
    for (int i = tid; i < 4096; i += FTH) sA[(i >> 6) * 66 + (i & 63)] = g_adj[i];
    for (int i = tid; i < 2048; i += FTH) ((float2*)sPreb)[i] = g_preb1p[i];
    if (tid < 384) sW1[tid] = gw1[tid];
    if (tid < 32) {
        ((float2*)sW3e)[tid] = make_float2(gw3[4 * tid],     gw3[4 * tid + 2]);
        ((float2*)sW3o)[tid] = make_float2(gw3[4 * tid + 1], gw3[4 * tid + 3]);
        sGc[tid] = gcw1[tid]; sGc[32 + tid] = gcb1[tid]; sGc[64 + tid] = gcw2[tid];
    }
    if (tid < 64) sB2[tid] = gb2[tid];
    if (tid == 0) { sCst[0] = gcb2[0]; sCst[1] = gb3[0]; sCst[2] = gb3[1]; }

    int n    = tid & 63;
    int r    = tid >> 6;      // 0..7
    int lane = tid & 31;
    int warp = tid >> 5;      // 0..15
    int m0   = warp * 32;
    int qr   = lane >> 2;     // quad row 0..7
    int qc   = lane & 3;      // quad col 0..3

    for (int tile = blockIdx.x; tile < NTILES; tile += PGRID) {
        __syncthreads();

        int gidx = tile * FTH + tid;
        float s  = seed[gidx];
        float mm = mask[gidx];
        float xf = xfreq[gidx];
        float xi = xin[gidx];

        // ---- phi(s), packed pairs ----
        u64 sp = pk2(s, s);
        u64 accp = pk2(0.f, 0.f);
        const u64* gcW = (const u64*)sGc;
        const u64* gcB = (const u64*)(sGc + 32);
        const u64* gcV = (const u64*)(sGc + 64);
        #pragma unroll
        for (int hq = 0; hq < 16; ++hq) {
            u64 pre = ffma2(sp, gcW[hq], gcB[hq]);
            accp = ffma2(gelu2(pre), gcV[hq], accp);
        }
        float p0, p1; upk2(accp, p0, p1);
        sPm[r * 64 + n] = p0 + p1;
        __syncthreads();

        // ---- x_gcn (packed matvec) ----
        u64 xgp = pk2(0.f, 0.f);
        const u64* arow = (const u64*)(sA + n * 66);
        const u64* prow = (const u64*)(sPm + r * 64);
        #pragma unroll 8
        for (int m2 = 0; m2 < 32; ++m2)
            xgp = ffma2(arow[m2], prow[m2], xgp);
        float xg0, xg1; upk2(xgp, xg0, xg1);
        float xg = xg0 + xg1 + sCst[0];

        sXg[tid] = xg; sXf[tid] = xf; sMm[tid] = mm; sXi[tid] = xi;
        out_gcn[gidx] = xg;

        // ---- layer1 (packed, u64 weight loads) -> hs as tf32 ----
        u64 u0 = pk2(s, s), u1 = pk2(mm, mm), u2 = pk2(xg, xg);
        u64 u3 = pk2(xf, xf), u4 = pk2(xg - s, xg - s), u5 = pk2(xf - s, xf - s);
        const u64* W1p = (const u64*)sW1;             // [6][32] pairs
        const u64* prebp = (const u64*)sPreb;
        u32* hsu = (u32*)hs;
        #pragma unroll
        for (int jq = 0; jq < 16; ++jq) {
            u64 a0 = prebp[(2 * jq) * 64 + n];
            u64 a1 = prebp[(2 * jq + 1) * 64 + n];
            int p2 = jq * 2;
            a0 = ffma2(u0, W1p[0 * 32 + p2], a0); a1 = ffma2(u0, W1p[0 * 32 + p2 + 1], a1);
            a0 = ffma2(u1, W1p[1 * 32 + p2], a0); a1 = ffma2(u1, W1p[1 * 32 + p2 + 1], a1);
            a0 = ffma2(u2, W1p[2 * 32 + p2], a0); a1 = ffma2(u2, W1p[2 * 32 + p2 + 1], a1);
            a0 = ffma2(u3, W1p[3 * 32 + p2], a0); a1 = ffma2(u3, W1p[3 * 32 + p2 + 1], a1);
            a0 = ffma2(u4, W1p[4 * 32 + p2], a0); a1 = ffma2(u4, W1p[4 * 32 + p2 + 1], a1);
            a0 = ffma2(u5, W1p[5 * 32 + p2], a0); a1 = ffma2(u5, W1p[5 * 32 + p2 + 1], a1);
            u64 g0 = gelu2(a0);
            u64 g1 = gelu2(a1);
            float v0, v1, v2, v3;
            upk2(g0, v0, v1); upk2(g1, v2, v3);
            hsu[(4 * jq + 0) * HS_S + tid] = to_tf32(v0);
            hsu[(4 * jq + 1) * HS_S + tid] = to_tf32(v1);
            hsu[(4 * jq + 2) * HS_S + tid] = to_tf32(v2);
            hsu[(4 * jq + 3) * HS_S + tid] = to_tf32(v3);
        }
        __syncthreads();

        // ---- Phase B: layer2 via tf32 mma ----
        float acc[2][8][4];
        #pragma unroll
        for (int n8 = 0; n8 < 8; ++n8) {
            int j0 = n8 * 8 + qc * 2;
            float2 bb = *(const float2*)(sB2 + j0);
            #pragma unroll
            for (int mt = 0; mt < 2; ++mt) {
                acc[mt][n8][0] = bb.x; acc[mt][n8][1] = bb.y;
                acc[mt][n8][2] = bb.x; acc[mt][n8][3] = bb.y;
            }
        }

        const u32* hsub = (const u32*)hs;
        const u32* w2u  = (const u32*)sW2;
        int ar = m0 + qr;
        #pragma unroll
        for (int k8 = 0; k8 < 8; ++k8) {
            int kb = k8 * 8 + qc;
            const u32* h0 = hsub + kb * HS_S;
            const u32* h4 = hsub + (kb + 4) * HS_S;
            u32 a00 = h0[ar],      a01 = h0[ar + 8],  a02 = h4[ar],      a03 = h4[ar + 8];
            u32 a10 = h0[ar + 16], a11 = h0[ar + 24], a12 = h4[ar + 16], a13 = h4[ar + 24];
            const u32* b0p = w2u + kb * W2_S + qr;
            const u32* b1p = w2u + (kb + 4) * W2_S + qr;
            #pragma unroll
            for (int n8 = 0; n8 < 8; ++n8) {
                u32 b0 = b0p[n8 * 8];
                u32 b1 = b1p[n8 * 8];
                mma_tf32(acc[0][n8], a00, a01, a02, a03, b0, b1);
                mma_tf32(acc[1][n8], a10, a11, a12, a13, b0, b1);
            }
        }

        // ---- epilogue: gelu(h2) + layer3 + quad reduce + outputs ----
        const float2* w3e = (const float2*)sW3e;
        const float2* w3o = (const float2*)sW3o;
        #pragma unroll
        for (int mt = 0; mt < 2; ++mt) {
            #pragma unroll
            for (int half = 0; half < 2; ++half) {
                u64 lgP0 = pk2(0.f, 0.f), lgP1 = pk2(0.f, 0.f);
                #pragma unroll
                for (int n8 = 0; n8 < 8; ++n8) {
                    int j2 = n8 * 4 + qc;
                    u64 a = pk2(acc[mt][n8][2 * half], acc[mt][n8][2 * half + 1]);
                    u64 g = gelu2(a);
                    float2 we = w3e[j2], wo = w3o[j2];
                    lgP0 = ffma2(g, pk2(we.x, we.y), lgP0);
                    lgP1 = ffma2(g, pk2(wo.x, wo.y), lgP1);
                }
                float l0a, l0b, l1a, l1b;
                upk2(lgP0, l0a, l0b); upk2(lgP1, l1a, l1b);
                float lg0 = l0a + l0b, lg1 = l1a + l1b;
                lg0 += __shfl_xor_sync(0xffffffffu, lg0, 1);
                lg0 += __shfl_xor_sync(0xffffffffu, lg0, 2);
                lg1 += __shfl_xor_sync(0xffffffffu, lg1, 1);
                lg1 += __shfl_xor_sync(0xffffffffu, lg1, 2);

                if (qc == half + 2 * mt) {
                    int row = m0 + qr + 8 * half + 16 * mt;
                    int og  = tile * FTH + row;
                    lg0 += sCst[1]; lg1 += sCst[2];
                    float mxv = fmaxf(lg0, lg1);
                    float e0 = __expf(lg0 - mxv), e1 = __expf(lg1 - mxv);
                    float inv = __fdividef(1.0f, e0 + e1);
                    float g0 = e0 * inv, g1 = e1 * inv;
                    float xgr = sXg[row], xfr = sXf[row], mmr = sMm[row], xir = sXi[row];
                    float imputed  = fmaf(g0, xgr, g1 * xfr);
                    float complete = (mmr != 0.f) ? imputed : xir;
                    out_imp[og]  = imputed;
                    out_comp[og] = complete;
                    float2 gv; gv.x = g0; gv.y = g1;
                    *(float2*)(out_gate + (size_t)og * 2) = gv;
                }
            }
        }
    }
}

// ---------------------------------------------------------------------------
extern "C" void kernel_launch(void* const* d_in, const int* in_sizes, int n_in,
                              void* d_out, int out_size)
{
    const float* x     = (const float*)d_in[0];
    const float* mask  = (const float*)d_in[1];
    const int*   rid   = (const int*)  d_in[2];
    const float* emb   = (const float*)d_in[3];
    const float* gcw1  = (const float*)d_in[4];
    const float* gcb1  = (const float*)d_in[5];
    const float* gcw2  = (const float*)d_in[6];
    const float* gcb2  = (const float*)d_in[7];
    const float* fre   = (const float*)d_in[8];
    const float* fim   = (const float*)d_in[9];
    const float* rtab  = (const float*)d_in[10];
    const float* gw1   = (const float*)d_in[11];
    const float* gb1   = (const float*)d_in[12];
    const float* gw2   = (const float*)d_in[13];
    const float* gb2   = (const float*)d_in[14];
    const float* gw3   = (const float*)d_in[15];
    const float* gb3   = (const float*)d_in[16];
    float* out = (float*)d_out;

    cudaFuncSetAttribute(fused_kernel, cudaFuncAttributeMaxDynamicSharedMemorySize, SMEM_BYTES);

    adj_kernel<<<1, 64>>>(emb, rid, rtab, gw1, gb1, out + ADJ_OFF);
    filt_t_kernel<<<64, 256>>>(fre, fim);
    fill_sum_kernel<<<256, 256>>>(x, mask);
    fill_scan_kernel<<<8, 128>>>();
    fill_out_kernel<<<256, 256>>>(x, mask, out + SEED_OFF);
    fft_kernel<<<B_ * N_ / 2, 256>>>(out + FREQ_OFF);
    fused_kernel<<<PGRID, FTH, SMEM_BYTES>>>(
        out + SEED_OFF, mask, x, out + FREQ_OFF,
        gw1, gw2, gb2, gw3, gb3,
        gcw1, gcb1, gcw2, gcb2,
        out + GCN_OFF, out + IMP_OFF, out + COMP_OFF, out + GATE_OFF);
}

// round 9
// speedup vs baseline: 1.1572x; 1.0197x over previous
#include <cuda_runtime.h>
#include <cuda_bf16.h>
#include <math.h>

#define B_ 16
#define T_ 2048
#define N_ 64

// Output layout (flattened tuple in order)
#define SEED_OFF 0
#define GCN_OFF  2097152
#define FREQ_OFF 4194304
#define IMP_OFF  6291456
#define COMP_OFF 8388608
#define GATE_OFF 10485760
#define ADJ_OFF  14680064

typedef unsigned long long u64;
typedef unsigned int u32;

// Scratch (static device arrays: allowed)
// Chunk-summary scratch is laid out TRANSPOSED: s = (b*64 + n)*64 + c
__device__ float  g_adj[N_ * N_];
__device__ float2 g_preb1p[32 * N_];
__device__ float  g_first[65536], g_last[65536];
__device__ unsigned char g_has[65536];
__device__ float  g_pref[65536], g_suf[65536];
__device__ unsigned char g_prefh[65536], g_sufh[65536];
__device__ float  g_seedT[B_ * N_ * T_];        // [b][n][t] transposed seed
__device__ float  g_freT[N_ * 1025];            // [n][k]
__device__ float  g_fimT[N_ * 1025];

// ---- packed f32x2 helpers ---------------------------------------------------
__device__ __forceinline__ u64 pk2(float lo, float hi) {
    u64 r; asm("mov.b64 %0, {%1, %2};" : "=l"(r) : "f"(lo), "f"(hi)); return r;
}
__device__ __forceinline__ void upk2(u64 v, float& lo, float& hi) {
    asm("mov.b64 {%0, %1}, %2;" : "=f"(lo), "=f"(hi) : "l"(v));
}
__device__ __forceinline__ u64 ffma2(u64 a, u64 b, u64 c) {
    u64 d; asm("fma.rn.f32x2 %0, %1, %2, %3;" : "=l"(d) : "l"(a), "l"(b), "l"(c)); return d;
}
__device__ __forceinline__ u64 mul2(u64 a, u64 b) {
    u64 d; asm("mul.rn.f32x2 %0, %1, %2;" : "=l"(d) : "l"(a), "l"(b)); return d;
}

__device__ __forceinline__ float tanh_ap(float x) {
    float t; asm("tanh.approx.f32 %0, %1;" : "=f"(t) : "f"(x)); return t;
}

// packed pairwise gelu: 5 packed fma-pipe ops + 2 MUFU
__device__ __forceinline__ u64 gelu2(u64 x) {
    const u64 C1 = pk2(0.035677408136f, 0.035677408136f);
    const u64 C0 = pk2(0.7978845608028654f, 0.7978845608028654f);
    const u64 H  = pk2(0.5f, 0.5f);
    u64 x2 = mul2(x, x);
    u64 inner = ffma2(x2, C1, C0);
    u64 b = mul2(x, inner);
    float b0, b1; upk2(b, b0, b1);
    u64 t = pk2(tanh_ap(b0), tanh_ap(b1));
    u64 hx = mul2(x, H);
    return ffma2(hx, t, hx);
}

__device__ __forceinline__ u32 to_tf32(float v) {
    u32 r; asm("cvt.rna.tf32.f32 %0, %1;" : "=r"(r) : "f"(v)); return r;
}

__device__ __forceinline__ void mma_tf32(float* d,
    u32 a0, u32 a1, u32 a2, u32 a3, u32 b0, u32 b1)
{
    asm("mma.sync.aligned.m16n8k8.row.col.f32.tf32.tf32.f32 "
        "{%0,%1,%2,%3}, {%4,%5,%6,%7}, {%8,%9}, {%0,%1,%2,%3};"
        : "+f"(d[0]), "+f"(d[1]), "+f"(d[2]), "+f"(d[3])
        : "r"(a0), "r"(a1), "r"(a2), "r"(a3), "r"(b0), "r"(b1));
}

// ---------------------------------------------------------------------------
// Fill stage 1: 32-step chunk summaries -> transposed scratch (b,n,c)
// ---------------------------------------------------------------------------
__global__ void __launch_bounds__(256) fill_sum_kernel(
    const float* __restrict__ x, const float* __restrict__ mask)
{
    int g = blockIdx.x * 256 + threadIdx.x;
    int n = g & 63;
    int c = (g >> 6) & 63;
    int b = g >> 12;
    int base = ((b * T_) + c * 32) * N_ + n;
    float first = 0.f, last = 0.f; bool has = false;
    #pragma unroll
    for (int t = 0; t < 32; ++t) {
        int idx = base + t * N_;
        float v = x[idx];
        bool obs = (mask[idx] == 0.f);
        if (obs) { if (!has) first = v; last = v; has = true; }
    }
    int s = ((b << 6) + n) * 64 + c;    // transposed
    g_first[s] = first; g_last[s] = last; g_has[s] = (unsigned char)has;
}

// ---------------------------------------------------------------------------
// Fill stage 2: per-(b,n) scan over 64 contiguous chunks, registers only.
// ---------------------------------------------------------------------------
__global__ void __launch_bounds__(128) fill_scan_kernel()
{
    int g = blockIdx.x * 128 + threadIdx.x;   // 0..1023 == (b*64+n)
    int base = g * 64;

    float fi[64], la[64];
    unsigned char ha[64];
    #pragma unroll
    for (int q = 0; q < 16; ++q) {
        *(float4*)(fi + q * 4) = *(const float4*)(g_first + base + q * 4);
        *(float4*)(la + q * 4) = *(const float4*)(g_last + base + q * 4);
    }
    #pragma unroll
    for (int q = 0; q < 4; ++q)
        *(uint4*)(ha + q * 16) = *(const uint4*)(g_has + base + q * 16);

    float pr[64], su[64];
    unsigned char prh[64], suh[64];
    float pv = 0.f; bool ph = false;
    #pragma unroll
    for (int c = 0; c < 64; ++c) {
        pr[c] = pv; prh[c] = (unsigned char)ph;
        if (ha[c]) { pv = la[c]; ph = true; }
    }
    float sv = 0.f; bool sh = false;
    #pragma unroll
    for (int c = 63; c >= 0; --c) {
        su[c] = sv; suh[c] = (unsigned char)sh;
        if (ha[c]) { sv = fi[c]; sh = true; }
    }

    #pragma unroll
    for (int q = 0; q < 16; ++q) {
        *(float4*)(g_pref + base + q * 4) = *(const float4*)(pr + q * 4);
        *(float4*)(g_suf  + base + q * 4) = *(const float4*)(su + q * 4);
    }
    #pragma unroll
    for (int q = 0; q < 4; ++q) {
        *(uint4*)(g_prefh + base + q * 16) = *(const uint4*)(prh + q * 16);
        *(uint4*)(g_sufh  + base + q * 16) = *(const uint4*)(suh + q * 16);
    }
}

// ---------------------------------------------------------------------------
// Fill stage 3: writes seed (normal) + g_seedT (transposed)
// ---------------------------------------------------------------------------
__global__ void __launch_bounds__(256) fill_out_kernel(
    const float* __restrict__ x, const float* __restrict__ mask,
    float* __restrict__ seed)
{
    int g = blockIdx.x * 256 + threadIdx.x;
    int n = g & 63;
    int c = (g >> 6) & 63;
    int b = g >> 12;
    int base = ((b * T_) + c * 32) * N_ + n;
    int s = ((b << 6) + n) * 64 + c;    // transposed scratch index
    float* tdst = g_seedT + ((size_t)(b * 64 + n)) * T_ + c * 32;

    float fv = g_pref[s]; bool fh = (bool)g_prefh[s];
    float vals[32];
    unsigned obsm = 0u, fam = 0u;
    #pragma unroll
    for (int t = 0; t < 32; ++t) {
        int idx = base + t * N_;
        float v = x[idx];
        bool obs = (mask[idx] == 0.f);
        if (obs) { fv = v; fh = true; obsm |= (1u << t); }
        vals[t] = fv;
        if (fh) fam |= (1u << t);
    }
    float bv = g_suf[s]; bool bh = (bool)g_sufh[s];
    #pragma unroll
    for (int t = 31; t >= 0; --t) {
        bool obs = (obsm >> t) & 1u;
        bool fa  = (fam  >> t) & 1u;
        float v = vals[t];
        if (obs) { bv = v; bh = true; }
        float out;
        if (obs)            out = v;
        else if (fa && bh)  out = 0.5f * (v + bv);
        else if (fa)        out = v;
        else if (bh)        out = bv;
        else                out = 0.f;
        seed[base + t * N_] = out;
        tdst[t] = out;
    }
}

// ---------------------------------------------------------------------------
// Filter transpose: freT[n][k] = fre[k][n]  (one-time, tiny)
// ---------------------------------------------------------------------------
__global__ void __launch_bounds__(256) filt_t_kernel(
    const float* __restrict__ fre, const float* __restrict__ fim)
{
    int n = blockIdx.x;
    for (int k = threadIdx.x; k < 1025; k += 256) {
        g_freT[n * 1025 + k] = fre[(size_t)k * N_ + n];
        g_fimT[n * 1025 + k] = fim[(size_t)k * N_ + n];
    }
}

// ---------------------------------------------------------------------------
// Kernel 2: adjacency + rate-embed pre-bias
// ---------------------------------------------------------------------------
__global__ void __launch_bounds__(64) adj_kernel(
    const float* __restrict__ emb, const int* __restrict__ rate_id,
    const float* __restrict__ rate_table, const float* __restrict__ gw1,
    const float* __restrict__ gb1, float* __restrict__ out_adj)
{
    __shared__ float sE[64 * 32];
    int tid = threadIdx.x;
    for (int i = tid; i < 64 * 32; i += 64) sE[i] = emb[i];
    __syncthreads();

    float sc[64];
    float mx = -1e30f;
    #pragma unroll
    for (int m = 0; m < 64; ++m) {
        float d = 0.f;
        #pragma unroll
        for (int h = 0; h < 32; ++h) d = fmaf(sE[tid * 32 + h], sE[m * 32 + h], d);
        d = fmaxf(d, 0.f);
        sc[m] = d; mx = fmaxf(mx, d);
    }
    float sum = 0.f;
    #pragma unroll
    for (int m = 0; m < 64; ++m) { float e = __expf(sc[m] - mx); sc[m] = e; sum += e; }
    float inv = 1.0f / sum;
    #pragma unroll
    for (int m = 0; m < 64; ++m) {
        float a = sc[m] * inv;
        g_adj[tid * 64 + m] = a;
        out_adj[tid * 64 + m] = a;
    }
    int rid = rate_id[tid];
    for (int j2 = 0; j2 < 32; ++j2) {
        float v0 = gb1[2 * j2], v1 = gb1[2 * j2 + 1];
        #pragma unroll
        for (int e = 0; e < 16; ++e) {
            float rt = rate_table[rid * 16 + e];
            v0 = fmaf(rt, gw1[(6 + e) * 64 + 2 * j2], v0);
            v1 = fmaf(rt, gw1[(6 + e) * 64 + 2 * j2 + 1], v1);
        }
        g_preb1p[j2 * 64 + tid] = make_float2(v0, v1);
    }
}

// ---------------------------------------------------------------------------
// Kernel 3: packed-pair radix-2 FFT filter; coalesced loads
// ---------------------------------------------------------------------------
__global__ void __launch_bounds__(256) fft_kernel(
    float* __restrict__ xfreq)
{
    __shared__ float re[2048], im[2048], twr[1024], twi[1024];
    int tid = threadIdx.x;
    int b = blockIdx.x >> 5;
    int p = blockIdx.x & 31;
    int n0 = p * 2;
    const float* src0 = g_seedT + ((size_t)(b * 64 + n0)) * T_;
    const float* src1 = src0 + T_;

    for (int j = tid; j < 1024; j += 256) {
        float s, c;
        sincosf(-6.28318530717958647692f * (float)j * (1.0f / 2048.0f), &s, &c);
        twr[j] = c; twi[j] = s;
    }
    for (int t = tid; t < 2048; t += 256) {
        re[t] = src0[t];
        im[t] = src1[t];
    }

    for (int s = 10; s >= 0; --s) {
        int half = 1 << s;
        __syncthreads();
        for (int bi = tid; bi < 1024; bi += 256) {
            int j = bi & (half - 1);
            int i1 = ((bi >> s) << (s + 1)) | j;
            int i2 = i1 + half;
            int tj = j << (10 - s);
            float wr = twr[tj], wi = twi[tj];
            float ar = re[i1], ai = im[i1], br = re[i2], b2 = im[i2];
            re[i1] = ar + br; im[i1] = ai + b2;
            float dr = ar - br, di = ai - b2;
            re[i2] = dr * wr - di * wi;
            im[i2] = dr * wi + di * wr;
        }
    }
    __syncthreads();

    const float* fT0r = g_freT + n0 * 1025;
    const float* fT0i = g_fimT + n0 * 1025;
    const float* fT1r = fT0r + 1025;
    const float* fT1i = fT0i + 1025;
    for (int k = tid; k <= 1024; k += 256) {
        int km = (2048 - k) & 2047;
        int pk = __brev(k) >> 21;
        int pm = __brev(km) >> 21;
        float zr = re[pk], zi = im[pk];
        float yr = re[pm], yi = im[pm];
        float x1r = 0.5f * (zr + yr), x1i = 0.5f * (zi - yi);
        float x2r = 0.5f * (zi + yi), x2i = 0.5f * (yr - zr);
        float h1r = fT0r[k], h1i = fT0i[k];
        float h2r = fT1r[k], h2i = fT1i[k];
        float y1r = x1r * h1r - x1i * h1i, y1i = x1r * h1i + x1i * h1r;
        float y2r = x2r * h2r - x2i * h2i, y2i = x2r * h2i + x2i * h2r;
        if (k == 0 || k == 1024) { y1i = 0.f; y2i = 0.f; }
        re[pk] = y1r - y2i; im[pk] = y1i + y2r;
        if (k > 0 && k < 1024) { re[pm] = y1r + y2i; im[pm] = y2r - y1i; }
    }

    for (int s = 0; s <= 10; ++s) {
        int half = 1 << s;
        __syncthreads();
        for (int bi = tid; bi < 1024; bi += 256) {
            int j = bi & (half - 1);
            int i1 = ((bi >> s) << (s + 1)) | j;
            int i2 = i1 + half;
            int tj = j << (10 - s);
            float wr = twr[tj], wi = -twi[tj];
            float br = re[i2], b2 = im[i2];
            float tr = br * wr - b2 * wi, ti = br * wi + b2 * wr;
            float ar = re[i1], ai = im[i1];
            re[i1] = ar + tr; im[i1] = ai + ti;
            re[i2] = ar - tr; im[i2] = ai - ti;
        }
    }
    __syncthreads();

    float* dst = xfreq + (size_t)b * T_ * N_ + n0;
    const float scl = 1.0f / 2048.0f;
    for (int t = tid; t < 2048; t += 256) {
        float2 v; v.x = re[t] * scl; v.y = im[t] * scl;
        *(float2*)(dst + (size_t)t * N_) = v;
    }
}

// ---------------------------------------------------------------------------
// Kernel 4 v7: 256-thread CTAs, 2 CTAs/SM (decoupled phases). tf32 mma layer2.
// preb1 read from global (L1-resident) to fit 2x smem in carveout.
// ---------------------------------------------------------------------------
#define FTH 256
#define HS_S 264
#define W2_S 72
#define NTILES (B_ * T_ * N_ / FTH)   // 8192
#define PGRID 296
// floats: hs 16896 + w2 4608 + adj 4224 + w1 384 + w3 128 + b2 64 + gc 96
//         + pm 256 + xg/xf/mm/xi 1024 + cst 4 = 27684
#define SMEM_BYTES (27684 * 4)

__global__ void __launch_bounds__(FTH, 2) fused_kernel(
    const float* __restrict__ seed, const float* __restrict__ mask,
    const float* __restrict__ xin, const float* __restrict__ xfreq,
    const float* __restrict__ gw1, const float* __restrict__ gw2,
    const float* __restrict__ gb2, const float* __restrict__ gw3,
    const float* __restrict__ gb3,
    const float* __restrict__ gcw1, const float* __restrict__ gcb1,
    const float* __restrict__ gcw2, const float* __restrict__ gcb2,
    float* __restrict__ out_gcn, float* __restrict__ out_imp,
    float* __restrict__ out_comp, float* __restrict__ out_gate)
{
    extern __shared__ float sm[];
    float* hs    = sm;                    // [64][264] (tf32 bits)
    float* sW2   = hs    + 64 * HS_S;     // [64][72] (tf32 bits)
    float* sA    = sW2   + 64 * W2_S;     // [64][66]
    float* sW1   = sA    + 64 * 66;       // [6][64]
    float* sW3e  = sW1   + 384;           // [32] float2
    float* sW3o  = sW3e  + 64;            // [32] float2
    float* sB2   = sW3o  + 64;            // [64]
    float* sGc   = sB2   + 64;            // [96]
    float* sPm   = sGc   + 96;            // [4][64]
    float* sXg   = sPm   + FTH;
    float* sXf   = sXg   + FTH;
    float* sMm   = sXf   + FTH;
    float* sXi   = sMm   + FTH;
    float* sCst  = sXi   + FTH;           // [4]

    int tid = threadIdx.x;

    // ---- stage weights once ----
    for (int i = tid; i < 4096; i += FTH) {
        int k = i >> 6, j = i & 63;
        ((u32*)sW2)[k * W2_S + j] = to_tf32(gw2[i]);
    }
    for (int i = tid; i < 4096; i += FTH) sA[(i >> 6) * 66 + (i & 63)] = g_adj[i];
    for (int i = tid; i < 384; i += FTH) sW1[i] = gw1[i];
    if (tid < 32) {
        ((float2*)sW3e)[tid] = make_float2(gw3[4 * tid],     gw3[4 * tid + 2]);
        ((float2*)sW3o)[tid] = make_float2(gw3[4 * tid + 1], gw3[4 * tid + 3]);
        sGc[tid] = gcw1[tid]; sGc[32 + tid] = gcb1[tid]; sGc[64 + tid] = gcw2[tid];
    }
    if (tid < 64) sB2[tid] = gb2[tid];
    if (tid == 0) { sCst[0] = gcb2[0]; sCst[1] = gb3[0]; sCst[2] = gb3[1]; }

    int n    = tid & 63;
    int r    = tid >> 6;      // 0..3
    int lane = tid & 31;
    int warp = tid >> 5;      // 0..7
    int m0   = warp * 32;
    int qr   = lane >> 2;     // quad row 0..7
    int qc   = lane & 3;      // quad col 0..3

    for (int tile = blockIdx.x; tile < NTILES; tile += PGRID) {
        __syncthreads();

        int gidx = tile * FTH + tid;
        float s  = seed[gidx];
        float mm = mask[gidx];
        float xf = xfreq[gidx];
        float xi = xin[gidx];

        // ---- phi(s), packed pairs ----
        u64 sp = pk2(s, s);
        u64 accp = pk2(0.f, 0.f);
        const u64* gcW = (const u64*)sGc;
        const u64* gcB = (const u64*)(sGc + 32);
        const u64* gcV = (const u64*)(sGc + 64);
        #pragma unroll
        for (int hq = 0; hq < 16; ++hq) {
            u64 pre = ffma2(sp, gcW[hq], gcB[hq]);
            accp = ffma2(gelu2(pre), gcV[hq], accp);
        }
        float p0, p1; upk2(accp, p0, p1);
        sPm[r * 64 + n] = p0 + p1;
        __syncthreads();

        // ---- x_gcn (packed matvec) ----
        u64 xgp = pk2(0.f, 0.f);
        const u64* arow = (const u64*)(sA + n * 66);
        const u64* prow = (const u64*)(sPm + r * 64);
        #pragma unroll 8
        for (int m2 = 0; m2 < 32; ++m2)
            xgp = ffma2(arow[m2], prow[m2], xgp);
        float xg0, xg1; upk2(xgp, xg0, xg1);
        float xg = xg0 + xg1 + sCst[0];

        sXg[tid] = xg; sXf[tid] = xf; sMm[tid] = mm; sXi[tid] = xi;
        out_gcn[gidx] = xg;

        // ---- layer1 (packed; preb1 from global/L1) -> hs as tf32 ----
        u64 u0 = pk2(s, s), u1 = pk2(mm, mm), u2 = pk2(xg, xg);
        u64 u3 = pk2(xf, xf), u4 = pk2(xg - s, xg - s), u5 = pk2(xf - s, xf - s);
        const u64* W1p = (const u64*)sW1;             // [6][32] pairs
        const u64* prebp = (const u64*)g_preb1p;
        u32* hsu = (u32*)hs;
        #pragma unroll
        for (int jq = 0; jq < 16; ++jq) {
            u64 a0 = __ldg(prebp + (2 * jq) * 64 + n);
            u64 a1 = __ldg(prebp + (2 * jq + 1) * 64 + n);
            int p2 = jq * 2;
            a0 = ffma2(u0, W1p[0 * 32 + p2], a0); a1 = ffma2(u0, W1p[0 * 32 + p2 + 1], a1);
            a0 = ffma2(u1, W1p[1 * 32 + p2], a0); a1 = ffma2(u1, W1p[1 * 32 + p2 + 1], a1);
            a0 = ffma2(u2, W1p[2 * 32 + p2], a0); a1 = ffma2(u2, W1p[2 * 32 + p2 + 1], a1);
            a0 = ffma2(u3, W1p[3 * 32 + p2], a0); a1 = ffma2(u3, W1p[3 * 32 + p2 + 1], a1);
            a0 = ffma2(u4, W1p[4 * 32 + p2], a0); a1 = ffma2(u4, W1p[4 * 32 + p2 + 1], a1);
            a0 = ffma2(u5, W1p[5 * 32 + p2], a0); a1 = ffma2(u5, W1p[5 * 32 + p2 + 1], a1);
            u64 g0 = gelu2(a0);
            u64 g1 = gelu2(a1);
            float v0, v1, v2, v3;
            upk2(g0, v0, v1); upk2(g1, v2, v3);
            hsu[(4 * jq + 0) * HS_S + tid] = to_tf32(v0);
            hsu[(4 * jq + 1) * HS_S + tid] = to_tf32(v1);
            hsu[(4 * jq + 2) * HS_S + tid] = to_tf32(v2);
            hsu[(4 * jq + 3) * HS_S + tid] = to_tf32(v3);
        }
        __syncthreads();

        // ---- Phase B: layer2 via tf32 mma ----
        float acc[2][8][4];
        #pragma unroll
        for (int n8 = 0; n8 < 8; ++n8) {
            int j0 = n8 * 8 + qc * 2;
            float2 bb = *(const float2*)(sB2 + j0);
            #pragma unroll
            for (int mt = 0; mt < 2; ++mt) {
                acc[mt][n8][0] = bb.x; acc[mt][n8][1] = bb.y;
                acc[mt][n8][2] = bb.x; acc[mt][n8][3] = bb.y;
            }
        }

        const u32* hsub = (const u32*)hs;
        const u32* w2u  = (const u32*)sW2;
        int ar = m0 + qr;
        #pragma unroll
        for (int k8 = 0; k8 < 8; ++k8) {
            int kb = k8 * 8 + qc;
            const u32* h0 = hsub + kb * HS_S;
            const u32* h4 = hsub + (kb + 4) * HS_S;
            u32 a00 = h0[ar],      a01 = h0[ar + 8],  a02 = h4[ar],      a03 = h4[ar + 8];
            u32 a10 = h0[ar + 16], a11 = h0[ar + 24], a12 = h4[ar + 16], a13 = h4[ar + 24];
            const u32* b0p = w2u + kb * W2_S + qr;
            const u32* b1p = w2u + (kb + 4) * W2_S + qr;
            #pragma unroll
            for (int n8 = 0; n8 < 8; ++n8) {
                u32 b0 = b0p[n8 * 8];
                u32 b1 = b1p[n8 * 8];
                mma_tf32(acc[0][n8], a00, a01, a02, a03, b0, b1);
                mma_tf32(acc[1][n8], a10, a11, a12, a13, b0, b1);
            }
        }

        // ---- epilogue: gelu(h2) + layer3 + quad reduce + outputs ----
        const float2* w3e = (const float2*)sW3e;
        const float2* w3o = (const float2*)sW3o;
        #pragma unroll
        for (int mt = 0; mt < 2; ++mt) {
            #pragma unroll
            for (int half = 0; half < 2; ++half) {
                u64 lgP0 = pk2(0.f, 0.f), lgP1 = pk2(0.f, 0.f);
                #pragma unroll
                for (int n8 = 0; n8 < 8; ++n8) {
                    int j2 = n8 * 4 + qc;
                    u64 a = pk2(acc[mt][n8][2 * half], acc[mt][n8][2 * half + 1]);
                    u64 g = gelu2(a);
                    float2 we = w3e[j2], wo = w3o[j2];
                    lgP0 = ffma2(g, pk2(we.x, we.y), lgP0);
                    lgP1 = ffma2(g, pk2(wo.x, wo.y), lgP1);
                }
                float l0a, l0b, l1a, l1b;
                upk2(lgP0, l0a, l0b); upk2(lgP1, l1a, l1b);
                float lg0 = l0a + l0b, lg1 = l1a + l1b;
                lg0 += __shfl_xor_sync(0xffffffffu, lg0, 1);
                lg0 += __shfl_xor_sync(0xffffffffu, lg0, 2);
                lg1 += __shfl_xor_sync(0xffffffffu, lg1, 1);
                lg1 += __shfl_xor_sync(0xffffffffu, lg1, 2);

                if (qc == half + 2 * mt) {
                    int row = m0 + qr + 8 * half + 16 * mt;
                    int og  = tile * FTH + row;
                    lg0 += sCst[1]; lg1 += sCst[2];
                    float mxv = fmaxf(lg0, lg1);
                    float e0 = __expf(lg0 - mxv), e1 = __expf(lg1 - mxv);
                    float inv = __fdividef(1.0f, e0 + e1);
                    float g0 = e0 * inv, g1 = e1 * inv;
                    float xgr = sXg[row], xfr = sXf[row], mmr = sMm[row], xir = sXi[row];
                    float imputed  = fmaf(g0, xgr, g1 * xfr);
                    float complete = (mmr != 0.f) ? imputed : xir;
                    out_imp[og]  = imputed;
                    out_comp[og] = complete;
                    float2 gv; gv.x = g0; gv.y = g1;
                    *(float2*)(out_gate + (size_t)og * 2) = gv;
                }
            }
        }
    }
}

// ---------------------------------------------------------------------------
extern "C" void kernel_launch(void* const* d_in, const int* in_sizes, int n_in,
                              void* d_out, int out_size)
{
    const float* x     = (const float*)d_in[0];
    const float* mask  = (const float*)d_in[1];
    const int*   rid   = (const int*)  d_in[2];
    const float* emb   = (const float*)d_in[3];
    const float* gcw1  = (const float*)d_in[4];
    const float* gcb1  = (const float*)d_in[5];
    const float* gcw2  = (const float*)d_in[6];
    const float* gcb2  = (const float*)d_in[7];
    const float* fre   = (const float*)d_in[8];
    const float* fim   = (const float*)d_in[9];
    const float* rtab  = (const float*)d_in[10];
    const float* gw1   = (const float*)d_in[11];
    const float* gb1   = (const float*)d_in[12];
    const float* gw2   = (const float*)d_in[13];
    const float* gb2   = (const float*)d_in[14];
    const float* gw3   = (const float*)d_in[15];
    const float* gb3   = (const float*)d_in[16];
    float* out = (float*)d_out;

    cudaFuncSetAttribute(fused_kernel, cudaFuncAttributeMaxDynamicSharedMemorySize, SMEM_BYTES);

    adj_kernel<<<1, 64>>>(emb, rid, rtab, gw1, gb1, out + ADJ_OFF);
    filt_t_kernel<<<64, 256>>>(fre, fim);
    fill_sum_kernel<<<256, 256>>>(x, mask);
    fill_scan_kernel<<<8, 128>>>();
    fill_out_kernel<<<256, 256>>>(x, mask, out + SEED_OFF);
    fft_kernel<<<B_ * N_ / 2, 256>>>(out + FREQ_OFF);
    fused_kernel<<<PGRID, FTH, SMEM_BYTES>>>(
        out + SEED_OFF, mask, x, out + FREQ_OFF,
        gw1, gw2, gb2, gw3, gb3,
        gcw1, gcb1, gcw2, gcb2,
        out + GCN_OFF, out + IMP_OFF, out + COMP_OFF, out + GATE_OFF);
}

// round 10
// speedup vs baseline: 1.1616x; 1.0038x over previous
#include <cuda_runtime.h>
#include <cuda_bf16.h>
#include <math.h>

#define B_ 16
#define T_ 2048
#define N_ 64

// Output layout (flattened tuple in order)
#define SEED_OFF 0
#define GCN_OFF  2097152
#define FREQ_OFF 4194304
#define IMP_OFF  6291456
#define COMP_OFF 8388608
#define GATE_OFF 10485760
#define ADJ_OFF  14680064

typedef unsigned long long u64;
typedef unsigned int u32;

// Scratch (static device arrays: allowed)
// Chunk-summary scratch TRANSPOSED: s = (b*64 + n)*64 + c
__device__ float  g_adj[N_ * N_];
__device__ float2 g_preb1p[32 * N_];
__device__ float  g_first[65536], g_last[65536];
__device__ unsigned char g_has[65536];
__device__ float  g_seedT[B_ * N_ * T_];        // [b][n][t]
__device__ float  g_freT[N_ * 1025];            // [n][k]
__device__ float  g_fimT[N_ * 1025];

// ---- packed f32x2 helpers ---------------------------------------------------
__device__ __forceinline__ u64 pk2(float lo, float hi) {
    u64 r; asm("mov.b64 %0, {%1, %2};" : "=l"(r) : "f"(lo), "f"(hi)); return r;
}
__device__ __forceinline__ void upk2(u64 v, float& lo, float& hi) {
    asm("mov.b64 {%0, %1}, %2;" : "=f"(lo), "=f"(hi) : "l"(v));
}
__device__ __forceinline__ u64 ffma2(u64 a, u64 b, u64 c) {
    u64 d; asm("fma.rn.f32x2 %0, %1, %2, %3;" : "=l"(d) : "l"(a), "l"(b), "l"(c)); return d;
}
__device__ __forceinline__ u64 mul2(u64 a, u64 b) {
    u64 d; asm("mul.rn.f32x2 %0, %1, %2;" : "=l"(d) : "l"(a), "l"(b)); return d;
}

__device__ __forceinline__ float tanh_ap(float x) {
    float t; asm("tanh.approx.f32 %0, %1;" : "=f"(t) : "f"(x)); return t;
}

// packed pairwise gelu
__device__ __forceinline__ u64 gelu2(u64 x) {
    const u64 C1 = pk2(0.035677408136f, 0.035677408136f);
    const u64 C0 = pk2(0.7978845608028654f, 0.7978845608028654f);
    const u64 H  = pk2(0.5f, 0.5f);
    u64 x2 = mul2(x, x);
    u64 inner = ffma2(x2, C1, C0);
    u64 b = mul2(x, inner);
    float b0, b1; upk2(b, b0, b1);
    u64 t = pk2(tanh_ap(b0), tanh_ap(b1));
    u64 hx = mul2(x, H);
    return ffma2(hx, t, hx);
}

__device__ __forceinline__ u32 to_tf32(float v) {
    u32 r; asm("cvt.rna.tf32.f32 %0, %1;" : "=r"(r) : "f"(v)); return r;
}

__device__ __forceinline__ void mma_tf32(float* d,
    u32 a0, u32 a1, u32 a2, u32 a3, u32 b0, u32 b1)
{
    asm("mma.sync.aligned.m16n8k8.row.col.f32.tf32.tf32.f32 "
        "{%0,%1,%2,%3}, {%4,%5,%6,%7}, {%8,%9}, {%0,%1,%2,%3};"
        : "+f"(d[0]), "+f"(d[1]), "+f"(d[2]), "+f"(d[3])
        : "r"(a0), "r"(a1), "r"(a2), "r"(a3), "r"(b0), "r"(b1));
}

// ---------------------------------------------------------------------------
// Kernel 0: prep = fill_sum (blk<256) + filter transpose (blk 256-319)
//                + adjacency/preb1 (blk 320). All independent.
// ---------------------------------------------------------------------------
__global__ void __launch_bounds__(256) prep_kernel(
    const float* __restrict__ x, const float* __restrict__ mask,
    const float* __restrict__ emb, const int* __restrict__ rate_id,
    const float* __restrict__ rate_table, const float* __restrict__ gw1,
    const float* __restrict__ gb1,
    const float* __restrict__ fre, const float* __restrict__ fim,
    float* __restrict__ out_adj)
{
    int blk = blockIdx.x;
    int tid = threadIdx.x;

    if (blk < 256) {
        // ---- fill_sum ----
        int g = blk * 256 + tid;
        int n = g & 63;
        int c = (g >> 6) & 63;
        int b = g >> 12;
        int base = ((b * T_) + c * 32) * N_ + n;
        float first = 0.f, last = 0.f; bool has = false;
        #pragma unroll
        for (int t = 0; t < 32; ++t) {
            int idx = base + t * N_;
            float v = x[idx];
            bool obs = (mask[idx] == 0.f);
            if (obs) { if (!has) first = v; last = v; has = true; }
        }
        int s = ((b << 6) + n) * 64 + c;
        g_first[s] = first; g_last[s] = last; g_has[s] = (unsigned char)has;
        return;
    }

    if (blk < 320) {
        // ---- filter transpose ----
        int n = blk - 256;
        for (int k = tid; k < 1025; k += 256) {
            g_freT[n * 1025 + k] = fre[(size_t)k * N_ + n];
            g_fimT[n * 1025 + k] = fim[(size_t)k * N_ + n];
        }
        return;
    }

    // ---- adjacency + rate-embed pre-bias (threads 0-63) ----
    __shared__ float sE[64 * 32];
    for (int i = tid; i < 64 * 32; i += 256) sE[i] = emb[i];
    __syncthreads();
    if (tid >= 64) return;

    float sc[64];
    float mx = -1e30f;
    #pragma unroll
    for (int m = 0; m < 64; ++m) {
        float d = 0.f;
        #pragma unroll
        for (int h = 0; h < 32; ++h) d = fmaf(sE[tid * 32 + h], sE[m * 32 + h], d);
        d = fmaxf(d, 0.f);
        sc[m] = d; mx = fmaxf(mx, d);
    }
    float sum = 0.f;
    #pragma unroll
    for (int m = 0; m < 64; ++m) { float e = __expf(sc[m] - mx); sc[m] = e; sum += e; }
    float inv = 1.0f / sum;
    #pragma unroll
    for (int m = 0; m < 64; ++m) {
        float a = sc[m] * inv;
        g_adj[tid * 64 + m] = a;
        out_adj[tid * 64 + m] = a;
    }
    int rid = rate_id[tid];
    for (int j2 = 0; j2 < 32; ++j2) {
        float v0 = gb1[2 * j2], v1 = gb1[2 * j2 + 1];
        #pragma unroll
        for (int e = 0; e < 16; ++e) {
            float rt = rate_table[rid * 16 + e];
            v0 = fmaf(rt, gw1[(6 + e) * 64 + 2 * j2], v0);
            v1 = fmaf(rt, gw1[(6 + e) * 64 + 2 * j2 + 1], v1);
        }
        g_preb1p[j2 * 64 + tid] = make_float2(v0, v1);
    }
}

// ---------------------------------------------------------------------------
// Kernel 1: fill_out v2 — in-block scan (threads 0-63 over contiguous
// transposed summaries) + fill phase. Block = (b, group of 4 chunks).
// ---------------------------------------------------------------------------
__global__ void __launch_bounds__(256) fill_out_kernel(
    const float* __restrict__ x, const float* __restrict__ mask,
    float* __restrict__ seed)
{
    __shared__ float sPr[256], sSu[256];
    __shared__ unsigned char sPrh[256], sSuh[256];

    int blk = blockIdx.x;
    int b = blk >> 4;
    int c0 = (blk & 15) * 4;
    int tid = threadIdx.x;

    if (tid < 64) {
        int bn = (b << 6) + tid;
        const float* fp = g_first + bn * 64;
        const float* lp = g_last + bn * 64;
        const unsigned char* hp = g_has + bn * 64;
        float pv = 0.f; bool ph = false;
        #pragma unroll 8
        for (int c = 0; c < 64; ++c) {
            unsigned d = (unsigned)(c - c0);
            if (d < 4u) { sPr[d * 64 + tid] = pv; sPrh[d * 64 + tid] = (unsigned char)ph; }
            if (hp[c]) { pv = lp[c]; ph = true; }
        }
        float sv = 0.f; bool sh = false;
        #pragma unroll 8
        for (int c = 63; c >= 0; --c) {
            unsigned d = (unsigned)(c - c0);
            if (d < 4u) { sSu[d * 64 + tid] = sv; sSuh[d * 64 + tid] = (unsigned char)sh; }
            if (hp[c]) { sv = fp[c]; sh = true; }
        }
    }
    __syncthreads();

    int n = tid & 63;
    int cl = tid >> 6;           // 0..3
    int c = c0 + cl;
    int base = ((b * T_) + c * 32) * N_ + n;
    float* tdst = g_seedT + ((size_t)(b * 64 + n)) * T_ + c * 32;

    float fv = sPr[cl * 64 + n]; bool fh = (bool)sPrh[cl * 64 + n];
    float vals[32];
    unsigned obsm = 0u, fam = 0u;
    #pragma unroll
    for (int t = 0; t < 32; ++t) {
        int idx = base + t * N_;
        float v = x[idx];
        bool obs = (mask[idx] == 0.f);
        if (obs) { fv = v; fh = true; obsm |= (1u << t); }
        vals[t] = fv;
        if (fh) fam |= (1u << t);
    }
    float bv = sSu[cl * 64 + n]; bool bh = (bool)sSuh[cl * 64 + n];
    #pragma unroll
    for (int t = 31; t >= 0; --t) {
        bool obs = (obsm >> t) & 1u;
        bool fa  = (fam  >> t) & 1u;
        float v = vals[t];
        if (obs) { bv = v; bh = true; }
        float out;
        if (obs)            out = v;
        else if (fa && bh)  out = 0.5f * (v + bv);
        else if (fa)        out = v;
        else if (bh)        out = bv;
        else                out = 0.f;
        seed[base + t * N_] = out;
        tdst[t] = out;
    }
}

// ---------------------------------------------------------------------------
// Kernel 2: packed-pair radix-2 FFT filter; coalesced loads
// ---------------------------------------------------------------------------
__global__ void __launch_bounds__(256) fft_kernel(
    float* __restrict__ xfreq)
{
    __shared__ float re[2048], im[2048], twr[1024], twi[1024];
    int tid = threadIdx.x;
    int b = blockIdx.x >> 5;
    int p = blockIdx.x & 31;
    int n0 = p * 2;
    const float* src0 = g_seedT + ((size_t)(b * 64 + n0)) * T_;
    const float* src1 = src0 + T_;

    for (int j = tid; j < 1024; j += 256) {
        float s, c;
        sincosf(-6.28318530717958647692f * (float)j * (1.0f / 2048.0f), &s, &c);
        twr[j] = c; twi[j] = s;
    }
    for (int t = tid; t < 2048; t += 256) {
        re[t] = src0[t];
        im[t] = src1[t];
    }

    for (int s = 10; s >= 0; --s) {
        int half = 1 << s;
        __syncthreads();
        for (int bi = tid; bi < 1024; bi += 256) {
            int j = bi & (half - 1);
            int i1 = ((bi >> s) << (s + 1)) | j;
            int i2 = i1 + half;
            int tj = j << (10 - s);
            float wr = twr[tj], wi = twi[tj];
            float ar = re[i1], ai = im[i1], br = re[i2], b2 = im[i2];
            re[i1] = ar + br; im[i1] = ai + b2;
            float dr = ar - br, di = ai - b2;
            re[i2] = dr * wr - di * wi;
            im[i2] = dr * wi + di * wr;
        }
    }
    __syncthreads();

    const float* fT0r = g_freT + n0 * 1025;
    const float* fT0i = g_fimT + n0 * 1025;
    const float* fT1r = fT0r + 1025;
    const float* fT1i = fT0i + 1025;
    for (int k = tid; k <= 1024; k += 256) {
        int km = (2048 - k) & 2047;
        int pk = __brev(k) >> 21;
        int pm = __brev(km) >> 21;
        float zr = re[pk], zi = im[pk];
        float yr = re[pm], yi = im[pm];
        float x1r = 0.5f * (zr + yr), x1i = 0.5f * (zi - yi);
        float x2r = 0.5f * (zi + yi), x2i = 0.5f * (yr - zr);
        float h1r = fT0r[k], h1i = fT0i[k];
        float h2r = fT1r[k], h2i = fT1i[k];
        float y1r = x1r * h1r - x1i * h1i, y1i = x1r * h1i + x1i * h1r;
        float y2r = x2r * h2r - x2i * h2i, y2i = x2r * h2i + x2i * h2r;
        if (k == 0 || k == 1024) { y1i = 0.f; y2i = 0.f; }
        re[pk] = y1r - y2i; im[pk] = y1i + y2r;
        if (k > 0 && k < 1024) { re[pm] = y1r + y2i; im[pm] = y2r - y1i; }
    }

    for (int s = 0; s <= 10; ++s) {
        int half = 1 << s;
        __syncthreads();
        for (int bi = tid; bi < 1024; bi += 256) {
            int j = bi & (half - 1);
            int i1 = ((bi >> s) << (s + 1)) | j;
            int i2 = i1 + half;
            int tj = j << (10 - s);
            float wr = twr[tj], wi = -twi[tj];
            float br = re[i2], b2 = im[i2];
            float tr = br * wr - b2 * wi, ti = br * wi + b2 * wr;
            float ar = re[i1], ai = im[i1];
            re[i1] = ar + tr; im[i1] = ai + ti;
            re[i2] = ar - tr; im[i2] = ai - ti;
        }
    }
    __syncthreads();

    float* dst = xfreq + (size_t)b * T_ * N_ + n0;
    const float scl = 1.0f / 2048.0f;
    for (int t = tid; t < 2048; t += 256) {
        float2 v; v.x = re[t] * scl; v.y = im[t] * scl;
        *(float2*)(dst + (size_t)t * N_) = v;
    }
}

// ---------------------------------------------------------------------------
// Kernel 3: fused (unchanged from R9): 256-thr CTAs, 2/SM, tf32 mma layer2.
// ---------------------------------------------------------------------------
#define FTH 256
#define HS_S 264
#define W2_S 72
#define NTILES (B_ * T_ * N_ / FTH)   // 8192
#define PGRID 296
#define SMEM_BYTES (27684 * 4)

__global__ void __launch_bounds__(FTH, 2) fused_kernel(
    const float* __restrict__ seed, const float* __restrict__ mask,
    const float* __restrict__ xin, const float* __restrict__ xfreq,
    const float* __restrict__ gw1, const float* __restrict__ gw2,
    const float* __restrict__ gb2, const float* __restrict__ gw3,
    const float* __restrict__ gb3,
    const float* __restrict__ gcw1, const float* __restrict__ gcb1,
    const float* __restrict__ gcw2, const float* __restrict__ gcb2,
    float* __restrict__ out_gcn, float* __restrict__ out_imp,
    float* __restrict__ out_comp, float* __restrict__ out_gate)
{
    extern __shared__ float sm[];
    float* hs    = sm;                    // [64][264] (tf32 bits)
    float* sW2   = hs    + 64 * HS_S;     // [64][72] (tf32 bits)
    float* sA    = sW2   + 64 * W2_S;     // [64][66]
    float* sW1   = sA    + 64 * 66;       // [6][64]
    float* sW3e  = sW1   + 384;           // [32] float2
    float* sW3o  = sW3e  + 64;            // [32] float2
    float* sB2   = sW3o  + 64;            // [64]
    float* sGc   = sB2   + 64;            // [96]
    float* sPm   = sGc   + 96;            // [4][64]
    float* sXg   = sPm   + FTH;
    float* sXf   = sXg   + FTH;
    float* sMm   = sXf   + FTH;
    float* sXi   = sMm   + FTH;
    float* sCst  = sXi   + FTH;           // [4]

    int tid = threadIdx.x;

    for (int i = tid; i < 4096; i += FTH) {
        int k = i >> 6, j = i & 63;
        ((u32*)sW2)[k * W2_S + j] = to_tf32(gw2[i]);
    }
    for (int i = tid; i < 4096; i += FTH) sA[(i >> 6) * 66 + (i & 63)] = g_adj[i];
    for (int i = tid; i < 384; i += FTH) sW1[i] = gw1[i];
    if (tid < 32) {
        ((float2*)sW3e)[tid] = make_float2(gw3[4 * tid],     gw3[4 * tid + 2]);
        ((float2*)sW3o)[tid] = make_float2(gw3[4 * tid + 1], gw3[4 * tid + 3]);
        sGc[tid] = gcw1[tid]; sGc[32 + tid] = gcb1[tid]; sGc[64 + tid] = gcw2[tid];
    }
    if (tid < 64) sB2[tid] = gb2[tid];
    if (tid == 0) { sCst[0] = gcb2[0]; sCst[1] = gb3[0]; sCst[2] = gb3[1]; }

    int n    = tid & 63;
    int r    = tid >> 6;      // 0..3
    int lane = tid & 31;
    int warp = tid >> 5;      // 0..7
    int m0   = warp * 32;
    int qr   = lane >> 2;     // quad row 0..7
    int qc   = lane & 3;      // quad col 0..3

    for (int tile = blockIdx.x; tile < NTILES; tile += PGRID) {
        __syncthreads();

        int gidx = tile * FTH + tid;
        float s  = seed[gidx];
        float mm = mask[gidx];
        float xf = xfreq[gidx];
        float xi = xin[gidx];

        // ---- phi(s), packed pairs ----
        u64 sp = pk2(s, s);
        u64 accp = pk2(0.f, 0.f);
        const u64* gcW = (const u64*)sGc;
        const u64* gcB = (const u64*)(sGc + 32);
        const u64* gcV = (const u64*)(sGc + 64);
        #pragma unroll
        for (int hq = 0; hq < 16; ++hq) {
            u64 pre = ffma2(sp, gcW[hq], gcB[hq]);
            accp = ffma2(gelu2(pre), gcV[hq], accp);
        }
        float p0, p1; upk2(accp, p0, p1);
        sPm[r * 64 + n] = p0 + p1;
        __syncthreads();

        // ---- x_gcn (packed matvec) ----
        u64 xgp = pk2(0.f, 0.f);
        const u64* arow = (const u64*)(sA + n * 66);
        const u64* prow = (const u64*)(sPm + r * 64);
        #pragma unroll 8
        for (int m2 = 0; m2 < 32; ++m2)
            xgp = ffma2(arow[m2], prow[m2], xgp);
        float xg0, xg1; upk2(xgp, xg0, xg1);
        float xg = xg0 + xg1 + sCst[0];

        sXg[tid] = xg; sXf[tid] = xf; sMm[tid] = mm; sXi[tid] = xi;
        out_gcn[gidx] = xg;

        // ---- layer1 (packed; preb1 from global/L1) -> hs as tf32 ----
        u64 u0 = pk2(s, s), u1 = pk2(mm, mm), u2 = pk2(xg, xg);
        u64 u3 = pk2(xf, xf), u4 = pk2(xg - s, xg - s), u5 = pk2(xf - s, xf - s);
        const u64* W1p = (const u64*)sW1;
        const u64* prebp = (const u64*)g_preb1p;
        u32* hsu = (u32*)hs;
        #pragma unroll
        for (int jq = 0; jq < 16; ++jq) {
            u64 a0 = __ldg(prebp + (2 * jq) * 64 + n);
            u64 a1 = __ldg(prebp + (2 * jq + 1) * 64 + n);
            int p2 = jq * 2;
            a0 = ffma2(u0, W1p[0 * 32 + p2], a0); a1 = ffma2(u0, W1p[0 * 32 + p2 + 1], a1);
            a0 = ffma2(u1, W1p[1 * 32 + p2], a0); a1 = ffma2(u1, W1p[1 * 32 + p2 + 1], a1);
            a0 = ffma2(u2, W1p[2 * 32 + p2], a0); a1 = ffma2(u2, W1p[2 * 32 + p2 + 1], a1);
            a0 = ffma2(u3, W1p[3 * 32 + p2], a0); a1 = ffma2(u3, W1p[3 * 32 + p2 + 1], a1);
            a0 = ffma2(u4, W1p[4 * 32 + p2], a0); a1 = ffma2(u4, W1p[4 * 32 + p2 + 1], a1);
            a0 = ffma2(u5, W1p[5 * 32 + p2], a0); a1 = ffma2(u5, W1p[5 * 32 + p2 + 1], a1);
            u64 g0 = gelu2(a0);
            u64 g1 = gelu2(a1);
            float v0, v1, v2, v3;
            upk2(g0, v0, v1); upk2(g1, v2, v3);
            hsu[(4 * jq + 0) * HS_S + tid] = to_tf32(v0);
            hsu[(4 * jq + 1) * HS_S + tid] = to_tf32(v1);
            hsu[(4 * jq + 2) * HS_S + tid] = to_tf32(v2);
            hsu[(4 * jq + 3) * HS_S + tid] = to_tf32(v3);
        }
        __syncthreads();

        // ---- Phase B: layer2 via tf32 mma ----
        float acc[2][8][4];
        #pragma unroll
        for (int n8 = 0; n8 < 8; ++n8) {
            int j0 = n8 * 8 + qc * 2;
            float2 bb = *(const float2*)(sB2 + j0);
            #pragma unroll
            for (int mt = 0; mt < 2; ++mt) {
                acc[mt][n8][0] = bb.x; acc[mt][n8][1] = bb.y;
                acc[mt][n8][2] = bb.x; acc[mt][n8][3] = bb.y;
            }
        }

        const u32* hsub = (const u32*)hs;
        const u32* w2u  = (const u32*)sW2;
        int ar = m0 + qr;
        #pragma unroll
        for (int k8 = 0; k8 < 8; ++k8) {
            int kb = k8 * 8 + qc;
            const u32* h0 = hsub + kb * HS_S;
            const u32* h4 = hsub + (kb + 4) * HS_S;
            u32 a00 = h0[ar],      a01 = h0[ar + 8],  a02 = h4[ar],      a03 = h4[ar + 8];
            u32 a10 = h0[ar + 16], a11 = h0[ar + 24], a12 = h4[ar + 16], a13 = h4[ar + 24];
            const u32* b0p = w2u + kb * W2_S + qr;
            const u32* b1p = w2u + (kb + 4) * W2_S + qr;
            #pragma unroll
            for (int n8 = 0; n8 < 8; ++n8) {
                u32 b0 = b0p[n8 * 8];
                u32 b1 = b1p[n8 * 8];
                mma_tf32(acc[0][n8], a00, a01, a02, a03, b0, b1);
                mma_tf32(acc[1][n8], a10, a11, a12, a13, b0, b1);
            }
        }

        // ---- epilogue ----
        const float2* w3e = (const float2*)sW3e;
        const float2* w3o = (const float2*)sW3o;
        #pragma unroll
        for (int mt = 0; mt < 2; ++mt) {
            #pragma unroll
            for (int half = 0; half < 2; ++half) {
                u64 lgP0 = pk2(0.f, 0.f), lgP1 = pk2(0.f, 0.f);
                #pragma unroll
                for (int n8 = 0; n8 < 8; ++n8) {
                    int j2 = n8 * 4 + qc;
                    u64 a = pk2(acc[mt][n8][2 * half], acc[mt][n8][2 * half + 1]);
                    u64 g = gelu2(a);
                    float2 we = w3e[j2], wo = w3o[j2];
                    lgP0 = ffma2(g, pk2(we.x, we.y), lgP0);
                    lgP1 = ffma2(g, pk2(wo.x, wo.y), lgP1);
                }
                float l0a, l0b, l1a, l1b;
                upk2(lgP0, l0a, l0b); upk2(lgP1, l1a, l1b);
                float lg0 = l0a + l0b, lg1 = l1a + l1b;
                lg0 += __shfl_xor_sync(0xffffffffu, lg0, 1);
                lg0 += __shfl_xor_sync(0xffffffffu, lg0, 2);
                lg1 += __shfl_xor_sync(0xffffffffu, lg1, 1);
                lg1 += __shfl_xor_sync(0xffffffffu, lg1, 2);

                if (qc == half + 2 * mt) {
                    int row = m0 + qr + 8 * half + 16 * mt;
                    int og  = tile * FTH + row;
                    lg0 += sCst[1]; lg1 += sCst[2];
                    float mxv = fmaxf(lg0, lg1);
                    float e0 = __expf(lg0 - mxv), e1 = __expf(lg1 - mxv);
                    float inv = __fdividef(1.0f, e0 + e1);
                    float g0 = e0 * inv, g1 = e1 * inv;
                    float xgr = sXg[row], xfr = sXf[row], mmr = sMm[row], xir = sXi[row];
                    float imputed  = fmaf(g0, xgr, g1 * xfr);
                    float complete = (mmr != 0.f) ? imputed : xir;
                    out_imp[og]  = imputed;
                    out_comp[og] = complete;
                    float2 gv; gv.x = g0; gv.y = g1;
                    *(float2*)(out_gate + (size_t)og * 2) = gv;
                }
            }
        }
    }
}

// ---------------------------------------------------------------------------
extern "C" void kernel_launch(void* const* d_in, const int* in_sizes, int n_in,
                              void* d_out, int out_size)
{
    const float* x     = (const float*)d_in[0];
    const float* mask  = (const float*)d_in[1];
    const int*   rid   = (const int*)  d_in[2];
    const float* emb   = (const float*)d_in[3];
    const float* gcw1  = (const float*)d_in[4];
    const float* gcb1  = (const float*)d_in[5];
    const float* gcw2  = (const float*)d_in[6];
    const float* gcb2  = (const float*)d_in[7];
    const float* fre   = (const float*)d_in[8];
    const float* fim   = (const float*)d_in[9];
    const float* rtab  = (const float*)d_in[10];
    const float* gw1   = (const float*)d_in[11];
    const float* gb1   = (const float*)d_in[12];
    const float* gw2   = (const float*)d_in[13];
    const float* gb2   = (const float*)d_in[14];
    const float* gw3   = (const float*)d_in[15];
    const float* gb3   = (const float*)d_in[16];
    float* out = (float*)d_out;

    cudaFuncSetAttribute(fused_kernel, cudaFuncAttributeMaxDynamicSharedMemorySize, SMEM_BYTES);

    prep_kernel<<<321, 256>>>(x, mask, emb, rid, rtab, gw1, gb1, fre, fim, out + ADJ_OFF);
    fill_out_kernel<<<256, 256>>>(x, mask, out + SEED_OFF);
    fft_kernel<<<B_ * N_ / 2, 256>>>(out + FREQ_OFF);
    fused_kernel<<<PGRID, FTH, SMEM_BYTES>>>(
        out + SEED_OFF, mask, x, out + FREQ_OFF,
        gw1, gw2, gb2, gw3, gb3,
        gcw1, gcb1, gcw2, gcb2,
        out + GCN_OFF, out + IMP_OFF, out + COMP_OFF, out + GATE_OFF);
}